// round 2
// baseline (speedup 1.0000x reference)
#include <cuda_runtime.h>
#include <cstdint>

#define D_MODEL 512
#define NHEADS  8
#define DK      64
#define NG      128
#define NGRAPHS 64
#define NNODES  8192
#define EPG     4096
#define NEDGES  262144

// ---------------- scratch (static device allocations; no cudaMalloc allowed) ----
__device__ float g_Q [NNODES * D_MODEL];
__device__ float g_K [NNODES * D_MODEL];
__device__ float g_V [NNODES * D_MODEL];
__device__ float g_O [NNODES * D_MODEL];
__device__ float g_EB[NEDGES * NHEADS];

// ---------------- fp32 SGEMM: C[M,N] = A[M,K] @ B[K,N] + bias[N] ---------------
// 128x128 tile, BK=8, 256 threads, 8x8 per thread (split 4+4 to reduce conflicts)
__global__ __launch_bounds__(256, 2)
void sgemm_kernel(const float* __restrict__ A, const float* __restrict__ B,
                  const float* __restrict__ bias, float* __restrict__ C,
                  int M, int N, int K) {
    __shared__ float As[8][128];   // transposed: As[k][m]
    __shared__ float Bs[8][128];   // Bs[k][n]

    const int tid = threadIdx.x;
    const int tx = tid & 15;
    const int ty = tid >> 4;
    const int bn = blockIdx.x * 128;
    const int bm = blockIdx.y * 128;

    const int arow = tid >> 1;          // 0..127
    const int acol = (tid & 1) * 4;     // 0 or 4
    const int brow = tid >> 5;          // 0..7
    const int bcol = (tid & 31) * 4;    // 0..124

    float acc[8][8];
    #pragma unroll
    for (int i = 0; i < 8; i++)
        #pragma unroll
        for (int j = 0; j < 8; j++) acc[i][j] = 0.f;

    for (int k0 = 0; k0 < K; k0 += 8) {
        float4 av = *(const float4*)(A + (size_t)(bm + arow) * K + k0 + acol);
        As[acol + 0][arow] = av.x;
        As[acol + 1][arow] = av.y;
        As[acol + 2][arow] = av.z;
        As[acol + 3][arow] = av.w;
        *(float4*)&Bs[brow][bcol] =
            *(const float4*)(B + (size_t)(k0 + brow) * N + bn + bcol);
        __syncthreads();

        #pragma unroll
        for (int k = 0; k < 8; k++) {
            float a[8], b[8];
            *(float4*)&a[0] = *(const float4*)&As[k][ty * 4];
            *(float4*)&a[4] = *(const float4*)&As[k][64 + ty * 4];
            *(float4*)&b[0] = *(const float4*)&Bs[k][tx * 4];
            *(float4*)&b[4] = *(const float4*)&Bs[k][64 + tx * 4];
            #pragma unroll
            for (int i = 0; i < 8; i++)
                #pragma unroll
                for (int j = 0; j < 8; j++)
                    acc[i][j] += a[i] * b[j];
        }
        __syncthreads();
    }

    #pragma unroll
    for (int i = 0; i < 8; i++) {
        int r = bm + ((i < 4) ? (ty * 4 + i) : (64 + ty * 4 + (i - 4)));
        #pragma unroll
        for (int jh = 0; jh < 2; jh++) {
            int c = bn + jh * 64 + tx * 4;
            float4 o;
            o.x = acc[i][jh * 4 + 0] + bias[c + 0];
            o.y = acc[i][jh * 4 + 1] + bias[c + 1];
            o.z = acc[i][jh * 4 + 2] + bias[c + 2];
            o.w = acc[i][jh * 4 + 3] + bias[c + 3];
            *(float4*)(C + (size_t)r * N + c) = o;
        }
    }
}

// ---------------- edge MLP: bias_e = relu(ea @ W1 + b1) @ W2 + b2 -> (E,8) -----
__global__ __launch_bounds__(256)
void edge_mlp_kernel(const float* __restrict__ ea,
                     const float* __restrict__ W1, const float* __restrict__ b1,
                     const float* __restrict__ W2, const float* __restrict__ b2,
                     float* __restrict__ eb) {
    __shared__ float4 w1v[D_MODEL];      // (W1[0][j],W1[1][j],W1[2][j],W1[3][j])
    __shared__ float  b1s[D_MODEL];
    __shared__ float  w2s[D_MODEL][8];   // W2 row j, heads 0..7

    const int tid = threadIdx.x;
    for (int j = tid; j < D_MODEL; j += blockDim.x) {
        w1v[j] = make_float4(W1[j], W1[D_MODEL + j], W1[2 * D_MODEL + j], W1[3 * D_MODEL + j]);
        b1s[j] = b1[j];
        #pragma unroll
        for (int h = 0; h < 8; h++) w2s[j][h] = W2[j * 8 + h];
    }
    __syncthreads();

    const int total = gridDim.x * blockDim.x;
    for (int e = blockIdx.x * blockDim.x + tid; e < NEDGES; e += total) {
        float4 a = *(const float4*)(ea + (size_t)e * 4);
        float acc0 = b2[0], acc1 = b2[1], acc2 = b2[2], acc3 = b2[3];
        float acc4 = b2[4], acc5 = b2[5], acc6 = b2[6], acc7 = b2[7];
        #pragma unroll 4
        for (int j = 0; j < D_MODEL; j++) {
            float4 w = w1v[j];
            float hj = fmaf(a.x, w.x, fmaf(a.y, w.y, fmaf(a.z, w.z, fmaf(a.w, w.w, b1s[j]))));
            hj = fmaxf(hj, 0.f);
            float4 u0 = *(const float4*)&w2s[j][0];
            float4 u1 = *(const float4*)&w2s[j][4];
            acc0 = fmaf(hj, u0.x, acc0);
            acc1 = fmaf(hj, u0.y, acc1);
            acc2 = fmaf(hj, u0.z, acc2);
            acc3 = fmaf(hj, u0.w, acc3);
            acc4 = fmaf(hj, u1.x, acc4);
            acc5 = fmaf(hj, u1.y, acc5);
            acc6 = fmaf(hj, u1.z, acc6);
            acc7 = fmaf(hj, u1.w, acc7);
        }
        float4 o0 = make_float4(acc0, acc1, acc2, acc3);
        float4 o1 = make_float4(acc4, acc5, acc6, acc7);
        *(float4*)(eb + (size_t)e * 8)     = o0;
        *(float4*)(eb + (size_t)e * 8 + 4) = o1;
    }
}

// ---------------- fused block-diagonal attention: one CTA per (g,h) ------------
// smem: K tile 32KB + V tile 32KB + S (128x129) 66KB  => 131584 B dynamic
__global__ __launch_bounds__(128)
void attn_kernel(const int* __restrict__ edge_index) {
    extern __shared__ float sm[];
    float* Kt = sm;                  // [128][64]
    float* Vt = sm + NG * DK;        // [128][64]
    float* S  = sm + 2 * NG * DK;    // [128][129] padded

    const int g = blockIdx.x >> 3;
    const int h = blockIdx.x & 7;
    const int tid = threadIdx.x;

    const float* Kg = g_K + (size_t)g * NG * D_MODEL + h * DK;
    const float* Vg = g_V + (size_t)g * NG * D_MODEL + h * DK;

    // cooperative K/V tile loads (coalesced 256B per row)
    for (int idx = tid; idx < NG * DK / 4; idx += 128) {
        int row = idx >> 4;        // 16 float4 per row
        int c4  = idx & 15;
        ((float4*)Kt)[row * 16 + c4] = *(const float4*)(Kg + (size_t)row * D_MODEL + c4 * 4);
        ((float4*)Vt)[row * 16 + c4] = *(const float4*)(Vg + (size_t)row * D_MODEL + c4 * 4);
    }

    // q row in registers
    float q[DK];
    const float* Qg = g_Q + (size_t)(g * NG + tid) * D_MODEL + h * DK;
    #pragma unroll
    for (int d = 0; d < DK; d += 4) {
        float4 v = *(const float4*)(Qg + d);
        q[d] = v.x; q[d + 1] = v.y; q[d + 2] = v.z; q[d + 3] = v.w;
    }
    __syncthreads();

    // scores: S[i][j] = scale * q_i . k_j   (4 partial sums to break FMA chain)
    const float scale = 0.125f;   // 1/sqrt(64)
    for (int j = 0; j < NG; j++) {
        float s0 = 0.f, s1 = 0.f, s2 = 0.f, s3 = 0.f;
        #pragma unroll
        for (int d = 0; d < DK; d += 4) {
            float4 kv = *(const float4*)(Kt + j * DK + d);
            s0 = fmaf(q[d],     kv.x, s0);
            s1 = fmaf(q[d + 1], kv.y, s1);
            s2 = fmaf(q[d + 2], kv.z, s2);
            s3 = fmaf(q[d + 3], kv.w, s3);
        }
        S[tid * 129 + j] = ((s0 + s1) + (s2 + s3)) * scale;
    }
    __syncthreads();

    // scatter precomputed edge bias into S (edges for graph g are contiguous)
    const int* srcp = edge_index;
    const int* dstp = edge_index + NEDGES;
    for (int t = tid; t < EPG; t += 128) {
        int e  = g * EPG + t;
        int ls = srcp[e] & (NG - 1);
        int ld = dstp[e] & (NG - 1);
        atomicAdd(&S[ls * 129 + ld], g_EB[(size_t)e * 8 + h]);
    }
    __syncthreads();

    // softmax over j (each thread owns row tid; bank-conflict-free via 129 pad)
    float m = -1e30f;
    for (int j = 0; j < NG; j++) m = fmaxf(m, S[tid * 129 + j]);
    float sum = 0.f;
    for (int j = 0; j < NG; j++) {
        float p = __expf(S[tid * 129 + j] - m);
        S[tid * 129 + j] = p;
        sum += p;
    }
    float inv = 1.f / sum;

    // out_i = (1/sum) * sum_j p_ij * V_j
    float acc[DK];
    #pragma unroll
    for (int d = 0; d < DK; d++) acc[d] = 0.f;
    for (int j = 0; j < NG; j++) {
        float p = S[tid * 129 + j];
        #pragma unroll
        for (int d = 0; d < DK; d += 4) {
            float4 v = *(const float4*)(Vt + j * DK + d);
            acc[d]     = fmaf(p, v.x, acc[d]);
            acc[d + 1] = fmaf(p, v.y, acc[d + 1]);
            acc[d + 2] = fmaf(p, v.z, acc[d + 2]);
            acc[d + 3] = fmaf(p, v.w, acc[d + 3]);
        }
    }

    float* Og = g_O + (size_t)(g * NG + tid) * D_MODEL + h * DK;
    #pragma unroll
    for (int d = 0; d < DK; d += 4) {
        float4 o;
        o.x = acc[d] * inv; o.y = acc[d + 1] * inv;
        o.z = acc[d + 2] * inv; o.w = acc[d + 3] * inv;
        *(float4*)(Og + d) = o;
    }
}

// ---------------- launcher -----------------------------------------------------
extern "C" void kernel_launch(void* const* d_in, const int* in_sizes, int n_in,
                              void* d_out, int out_size) {
    const float* x    = (const float*)d_in[0];
    const int*   eidx = (const int*)  d_in[1];
    const float* ea   = (const float*)d_in[2];
    // d_in[3] = batch (unused), d_in[4] = n_g (unused, fixed 128)
    const float* Wq = (const float*)d_in[5];
    const float* bq = (const float*)d_in[6];
    const float* Wk = (const float*)d_in[7];
    const float* bk = (const float*)d_in[8];
    const float* Wv = (const float*)d_in[9];
    const float* bv = (const float*)d_in[10];
    const float* Wo = (const float*)d_in[11];
    const float* bo = (const float*)d_in[12];
    const float* W1 = (const float*)d_in[13];
    const float* b1 = (const float*)d_in[14];
    const float* W2 = (const float*)d_in[15];
    const float* b2 = (const float*)d_in[16];
    float* out = (float*)d_out;

    float *Qp, *Kp, *Vp, *Op, *EBp;
    cudaGetSymbolAddress((void**)&Qp,  g_Q);
    cudaGetSymbolAddress((void**)&Kp,  g_K);
    cudaGetSymbolAddress((void**)&Vp,  g_V);
    cudaGetSymbolAddress((void**)&Op,  g_O);
    cudaGetSymbolAddress((void**)&EBp, g_EB);

    const int attn_smem = (2 * NG * DK + NG * 129) * (int)sizeof(float); // 131584
    cudaFuncSetAttribute(attn_kernel, cudaFuncAttributeMaxDynamicSharedMemorySize, attn_smem);

    dim3 ggrid(D_MODEL / 128, NNODES / 128);  // (4, 64)
    sgemm_kernel<<<ggrid, 256>>>(x, Wq, bq, Qp, NNODES, D_MODEL, D_MODEL);
    sgemm_kernel<<<ggrid, 256>>>(x, Wk, bk, Kp, NNODES, D_MODEL, D_MODEL);
    sgemm_kernel<<<ggrid, 256>>>(x, Wv, bv, Vp, NNODES, D_MODEL, D_MODEL);

    edge_mlp_kernel<<<NEDGES / 256, 256>>>(ea, W1, b1, W2, b2, EBp);

    attn_kernel<<<NGRAPHS * NHEADS, 128, attn_smem>>>(eidx);

    sgemm_kernel<<<ggrid, 256>>>(Op, Wo, bo, out, NNODES, D_MODEL, D_MODEL);
}

// round 7
// speedup vs baseline: 1.4333x; 1.4333x over previous
#include <cuda_runtime.h>
#include <cuda_bf16.h>
#include <cstdint>

#define D_MODEL 512
#define NHEADS  8
#define DK      64
#define NG      128
#define NGRAPHS 64
#define NNODES  8192
#define EPG     4096
#define NEDGES  262144
#define KPAD    40          // smem K stride (elems): conflict-free frag loads

// ---------------- scratch (static device allocations) ----------------------
__device__ float g_Q [NNODES * D_MODEL];
__device__ float g_K [NNODES * D_MODEL];
__device__ float g_V [NNODES * D_MODEL];
__device__ float g_O [NNODES * D_MODEL];
__device__ float g_EB[NEDGES * NHEADS];

__device__ __nv_bfloat16 g_Xhi[NNODES * D_MODEL];
__device__ __nv_bfloat16 g_Xlo[NNODES * D_MODEL];
__device__ __nv_bfloat16 g_Ohi[NNODES * D_MODEL];
__device__ __nv_bfloat16 g_Olo[NNODES * D_MODEL];
__device__ __nv_bfloat16 g_WThi[4 * D_MODEL * D_MODEL];  // [n][k] transposed
__device__ __nv_bfloat16 g_WTlo[4 * D_MODEL * D_MODEL];

// ---------------- helpers ---------------------------------------------------
__device__ __forceinline__ void split_bf16(float v, __nv_bfloat16& hi, __nv_bfloat16& lo) {
    hi = __float2bfloat16(v);
    lo = __float2bfloat16(v - __bfloat162float(hi));
}

__device__ __forceinline__ void mma16816(float* d, const uint32_t* a, uint32_t b0, uint32_t b1) {
    asm volatile(
        "mma.sync.aligned.m16n8k16.row.col.f32.bf16.bf16.f32 "
        "{%0,%1,%2,%3}, {%4,%5,%6,%7}, {%8,%9}, {%0,%1,%2,%3};"
        : "+f"(d[0]), "+f"(d[1]), "+f"(d[2]), "+f"(d[3])
        : "r"(a[0]), "r"(a[1]), "r"(a[2]), "r"(a[3]), "r"(b0), "r"(b1));
}

// ---------------- prep: elementwise hi/lo split ------------------------------
__global__ __launch_bounds__(256)
void prep_split(const float* __restrict__ X, __nv_bfloat16* __restrict__ hi,
                __nv_bfloat16* __restrict__ lo) {
    int i = (blockIdx.x * 256 + threadIdx.x) * 4;
    float4 v = *(const float4*)(X + i);
    __nv_bfloat16 h[4], l[4];
    split_bf16(v.x, h[0], l[0]);
    split_bf16(v.y, h[1], l[1]);
    split_bf16(v.z, h[2], l[2]);
    split_bf16(v.w, h[3], l[3]);
    *(uint2*)(hi + i) = *(uint2*)h;
    *(uint2*)(lo + i) = *(uint2*)l;
}

// ---------------- prep: weight transpose + split  W[k][n] -> WT[n][k] --------
__global__ __launch_bounds__(256)
void prep_w(const float* __restrict__ W, __nv_bfloat16* __restrict__ Thi,
            __nv_bfloat16* __restrict__ Tlo) {
    __shared__ float tile[32][33];
    const int k0 = blockIdx.y * 32, n0 = blockIdx.x * 32;
    const int tx = threadIdx.x & 31, ty = threadIdx.x >> 5;   // 8 rows/pass
    #pragma unroll
    for (int r = ty; r < 32; r += 8)
        tile[r][tx] = W[(size_t)(k0 + r) * D_MODEL + n0 + tx];
    __syncthreads();
    #pragma unroll
    for (int r = ty; r < 32; r += 8) {
        float v = tile[tx][r];            // = W[k0+tx][n0+r]
        __nv_bfloat16 h, l;
        split_bf16(v, h, l);
        size_t o = (size_t)(n0 + r) * D_MODEL + k0 + tx;
        Thi[o] = h;
        Tlo[o] = l;
    }
}

// ---------------- bf16x3 mma.sync GEMM: C = A@B + bias -----------------------
// A hi/lo: [M][512] bf16 row-major; BT hi/lo: [512][512] bf16 [n][k];
// CTA tile 128x128, BK=32, 256 threads (8 warps = 4M x 2N), warp tile 32x64.
__global__ __launch_bounds__(256, 2)
void gemm_mma(const __nv_bfloat16* __restrict__ Ahi, const __nv_bfloat16* __restrict__ Alo,
              const __nv_bfloat16* __restrict__ Bhi, const __nv_bfloat16* __restrict__ Blo,
              const float* __restrict__ bias, float* __restrict__ C) {
    __shared__ __nv_bfloat16 Ash[128 * KPAD], Asl[128 * KPAD];
    __shared__ __nv_bfloat16 Bsh[128 * KPAD], Bsl[128 * KPAD];

    const int tid  = threadIdx.x;
    const int lane = tid & 31, wid = tid >> 5;
    const int wm = (wid & 3) * 32;          // warp row base in tile
    const int wn = (wid >> 2) * 64;         // warp col base in tile
    const int bn = blockIdx.x * 128;
    const int bm = blockIdx.y * 128;
    const int grp = lane >> 2, th = lane & 3;

    float acc[2][8][4];
    #pragma unroll
    for (int mi = 0; mi < 2; mi++)
        #pragma unroll
        for (int ni = 0; ni < 8; ni++)
            #pragma unroll
            for (int j = 0; j < 4; j++) acc[mi][ni][j] = 0.f;

    const int lr = tid >> 2;                // 0..63 (row per pass)
    const int lc = (tid & 3) * 8;           // bf16 col (8 per uint4)

    for (int k0 = 0; k0 < D_MODEL; k0 += 32) {
        __syncthreads();
        #pragma unroll
        for (int p = 0; p < 2; p++) {
            int r = p * 64 + lr;
            *(uint4*)&Ash[r * KPAD + lc] = *(const uint4*)&Ahi[(size_t)(bm + r) * D_MODEL + k0 + lc];
            *(uint4*)&Asl[r * KPAD + lc] = *(const uint4*)&Alo[(size_t)(bm + r) * D_MODEL + k0 + lc];
            *(uint4*)&Bsh[r * KPAD + lc] = *(const uint4*)&Bhi[(size_t)(bn + r) * D_MODEL + k0 + lc];
            *(uint4*)&Bsl[r * KPAD + lc] = *(const uint4*)&Blo[(size_t)(bn + r) * D_MODEL + k0 + lc];
        }
        __syncthreads();

        #pragma unroll
        for (int ks = 0; ks < 32; ks += 16) {
            uint32_t ah[2][4], al[2][4];
            #pragma unroll
            for (int mi = 0; mi < 2; mi++) {
                int r0 = wm + mi * 16 + grp;
                int c0 = ks + th * 2;
                ah[mi][0] = *(const uint32_t*)&Ash[r0 * KPAD + c0];
                ah[mi][1] = *(const uint32_t*)&Ash[(r0 + 8) * KPAD + c0];
                ah[mi][2] = *(const uint32_t*)&Ash[r0 * KPAD + c0 + 8];
                ah[mi][3] = *(const uint32_t*)&Ash[(r0 + 8) * KPAD + c0 + 8];
                al[mi][0] = *(const uint32_t*)&Asl[r0 * KPAD + c0];
                al[mi][1] = *(const uint32_t*)&Asl[(r0 + 8) * KPAD + c0];
                al[mi][2] = *(const uint32_t*)&Asl[r0 * KPAD + c0 + 8];
                al[mi][3] = *(const uint32_t*)&Asl[(r0 + 8) * KPAD + c0 + 8];
            }
            #pragma unroll
            for (int ni = 0; ni < 8; ni++) {
                int nr = wn + ni * 8 + grp;
                int c0 = ks + th * 2;
                uint32_t bh0 = *(const uint32_t*)&Bsh[nr * KPAD + c0];
                uint32_t bh1 = *(const uint32_t*)&Bsh[nr * KPAD + c0 + 8];
                uint32_t bl0 = *(const uint32_t*)&Bsl[nr * KPAD + c0];
                uint32_t bl1 = *(const uint32_t*)&Bsl[nr * KPAD + c0 + 8];
                #pragma unroll
                for (int mi = 0; mi < 2; mi++) {
                    mma16816(acc[mi][ni], ah[mi], bh0, bh1);
                    mma16816(acc[mi][ni], ah[mi], bl0, bl1);
                    mma16816(acc[mi][ni], al[mi], bh0, bh1);
                }
            }
        }
    }

    // epilogue: c0,c1 at (row, th*2), c2,c3 at (row+8, th*2)
    #pragma unroll
    for (int mi = 0; mi < 2; mi++) {
        int row = bm + wm + mi * 16 + grp;
        #pragma unroll
        for (int ni = 0; ni < 8; ni++) {
            int col = bn + wn + ni * 8 + th * 2;
            float bx = bias[col], by = bias[col + 1];
            float2 o0 = make_float2(acc[mi][ni][0] + bx, acc[mi][ni][1] + by);
            float2 o1 = make_float2(acc[mi][ni][2] + bx, acc[mi][ni][3] + by);
            *(float2*)&C[(size_t)row * D_MODEL + col]       = o0;
            *(float2*)&C[(size_t)(row + 8) * D_MODEL + col] = o1;
        }
    }
}

// ---------------- edge MLP: 4 edges/thread (LDS amortized) -------------------
__global__ __launch_bounds__(256)
void edge_mlp_kernel(const float* __restrict__ ea,
                     const float* __restrict__ W1, const float* __restrict__ b1,
                     const float* __restrict__ W2, const float* __restrict__ b2,
                     float* __restrict__ eb) {
    __shared__ float4 w1v[D_MODEL];
    __shared__ float  b1s[D_MODEL];
    __shared__ float  w2s[D_MODEL][8];

    const int tid = threadIdx.x;
    for (int j = tid; j < D_MODEL; j += blockDim.x) {
        w1v[j] = make_float4(W1[j], W1[D_MODEL + j], W1[2 * D_MODEL + j], W1[3 * D_MODEL + j]);
        b1s[j] = b1[j];
        #pragma unroll
        for (int h = 0; h < 8; h++) w2s[j][h] = W2[j * 8 + h];
    }
    __syncthreads();

    const int base = blockIdx.x * 1024;
    float4 a[4];
    #pragma unroll
    for (int t = 0; t < 4; t++)
        a[t] = *(const float4*)(ea + (size_t)(base + t * 256 + tid) * 4);

    float acc[4][8];
    #pragma unroll
    for (int t = 0; t < 4; t++)
        #pragma unroll
        for (int h = 0; h < 8; h++) acc[t][h] = b2[h];

    #pragma unroll 2
    for (int j = 0; j < D_MODEL; j++) {
        float4 w = w1v[j];
        float bb = b1s[j];
        float4 u0 = *(const float4*)&w2s[j][0];
        float4 u1 = *(const float4*)&w2s[j][4];
        #pragma unroll
        for (int t = 0; t < 4; t++) {
            float hj = fmaf(a[t].x, w.x, fmaf(a[t].y, w.y, fmaf(a[t].z, w.z, fmaf(a[t].w, w.w, bb))));
            hj = fmaxf(hj, 0.f);
            acc[t][0] = fmaf(hj, u0.x, acc[t][0]);
            acc[t][1] = fmaf(hj, u0.y, acc[t][1]);
            acc[t][2] = fmaf(hj, u0.z, acc[t][2]);
            acc[t][3] = fmaf(hj, u0.w, acc[t][3]);
            acc[t][4] = fmaf(hj, u1.x, acc[t][4]);
            acc[t][5] = fmaf(hj, u1.y, acc[t][5]);
            acc[t][6] = fmaf(hj, u1.z, acc[t][6]);
            acc[t][7] = fmaf(hj, u1.w, acc[t][7]);
        }
    }
    #pragma unroll
    for (int t = 0; t < 4; t++) {
        int e = base + t * 256 + tid;
        *(float4*)(eb + (size_t)e * 8)     = *(float4*)&acc[t][0];
        *(float4*)(eb + (size_t)e * 8 + 4) = *(float4*)&acc[t][4];
    }
}

// ---------------- fused block-diagonal attention -----------------------------
__global__ __launch_bounds__(128)
void attn_kernel(const int* __restrict__ edge_index) {
    extern __shared__ float smf[];
    float* Kt = smf;
    float* Vt = smf + NG * DK;
    float* S  = smf + 2 * NG * DK;   // [128][129]

    const int g = blockIdx.x >> 3;
    const int h = blockIdx.x & 7;
    const int tid = threadIdx.x;

    const float* Kg = g_K + (size_t)g * NG * D_MODEL + h * DK;
    const float* Vg = g_V + (size_t)g * NG * D_MODEL + h * DK;

    for (int idx = tid; idx < NG * DK / 4; idx += 128) {
        int row = idx >> 4;
        int c4  = idx & 15;
        ((float4*)Kt)[row * 16 + c4] = *(const float4*)(Kg + (size_t)row * D_MODEL + c4 * 4);
        ((float4*)Vt)[row * 16 + c4] = *(const float4*)(Vg + (size_t)row * D_MODEL + c4 * 4);
    }

    float q[DK];
    const float* Qg = g_Q + (size_t)(g * NG + tid) * D_MODEL + h * DK;
    #pragma unroll
    for (int d = 0; d < DK; d += 4) {
        float4 v = *(const float4*)(Qg + d);
        q[d] = v.x; q[d + 1] = v.y; q[d + 2] = v.z; q[d + 3] = v.w;
    }
    __syncthreads();

    const float scale = 0.125f;
    for (int j = 0; j < NG; j++) {
        float s0 = 0.f, s1 = 0.f, s2 = 0.f, s3 = 0.f;
        #pragma unroll
        for (int d = 0; d < DK; d += 4) {
            float4 kv = *(const float4*)(Kt + j * DK + d);
            s0 = fmaf(q[d],     kv.x, s0);
            s1 = fmaf(q[d + 1], kv.y, s1);
            s2 = fmaf(q[d + 2], kv.z, s2);
            s3 = fmaf(q[d + 3], kv.w, s3);
        }
        S[tid * 129 + j] = ((s0 + s1) + (s2 + s3)) * scale;
    }
    __syncthreads();

    const int* srcp = edge_index;
    const int* dstp = edge_index + NEDGES;
    for (int t = tid; t < EPG; t += 128) {
        int e  = g * EPG + t;
        int ls = srcp[e] & (NG - 1);
        int ld = dstp[e] & (NG - 1);
        atomicAdd(&S[ls * 129 + ld], g_EB[(size_t)e * 8 + h]);
    }
    __syncthreads();

    float m = -1e30f;
    for (int j = 0; j < NG; j++) m = fmaxf(m, S[tid * 129 + j]);
    float sum = 0.f;
    for (int j = 0; j < NG; j++) {
        float p = __expf(S[tid * 129 + j] - m);
        S[tid * 129 + j] = p;
        sum += p;
    }
    float inv = 1.f / sum;

    float acc[DK];
    #pragma unroll
    for (int d = 0; d < DK; d++) acc[d] = 0.f;
    for (int j = 0; j < NG; j++) {
        float p = S[tid * 129 + j];
        #pragma unroll
        for (int d = 0; d < DK; d += 4) {
            float4 v = *(const float4*)(Vt + j * DK + d);
            acc[d]     = fmaf(p, v.x, acc[d]);
            acc[d + 1] = fmaf(p, v.y, acc[d + 1]);
            acc[d + 2] = fmaf(p, v.z, acc[d + 2]);
            acc[d + 3] = fmaf(p, v.w, acc[d + 3]);
        }
    }

    float* Og = g_O + (size_t)(g * NG + tid) * D_MODEL + h * DK;
    #pragma unroll
    for (int d = 0; d < DK; d += 4) {
        float4 o;
        o.x = acc[d] * inv; o.y = acc[d + 1] * inv;
        o.z = acc[d + 2] * inv; o.w = acc[d + 3] * inv;
        *(float4*)(Og + d) = o;
    }
}

// ---------------- launcher ---------------------------------------------------
extern "C" void kernel_launch(void* const* d_in, const int* in_sizes, int n_in,
                              void* d_out, int out_size) {
    const float* x    = (const float*)d_in[0];
    const int*   eidx = (const int*)  d_in[1];
    const float* ea   = (const float*)d_in[2];
    const float* Wq = (const float*)d_in[5];
    const float* bq = (const float*)d_in[6];
    const float* Wk = (const float*)d_in[7];
    const float* bk = (const float*)d_in[8];
    const float* Wv = (const float*)d_in[9];
    const float* bv = (const float*)d_in[10];
    const float* Wo = (const float*)d_in[11];
    const float* bo = (const float*)d_in[12];
    const float* W1 = (const float*)d_in[13];
    const float* b1 = (const float*)d_in[14];
    const float* W2 = (const float*)d_in[15];
    const float* b2 = (const float*)d_in[16];
    float* out = (float*)d_out;

    float *Qp, *Kp, *Vp, *Op, *EBp;
    __nv_bfloat16 *Xh, *Xl, *Oh, *Ol, *WTh, *WTl;
    cudaGetSymbolAddress((void**)&Qp,  g_Q);
    cudaGetSymbolAddress((void**)&Kp,  g_K);
    cudaGetSymbolAddress((void**)&Vp,  g_V);
    cudaGetSymbolAddress((void**)&Op,  g_O);
    cudaGetSymbolAddress((void**)&EBp, g_EB);
    cudaGetSymbolAddress((void**)&Xh,  g_Xhi);
    cudaGetSymbolAddress((void**)&Xl,  g_Xlo);
    cudaGetSymbolAddress((void**)&Oh,  g_Ohi);
    cudaGetSymbolAddress((void**)&Ol,  g_Olo);
    cudaGetSymbolAddress((void**)&WTh, g_WThi);
    cudaGetSymbolAddress((void**)&WTl, g_WTlo);

    const int attn_smem = (2 * NG * DK + NG * 129) * (int)sizeof(float);
    cudaFuncSetAttribute(attn_kernel, cudaFuncAttributeMaxDynamicSharedMemorySize, attn_smem);

    const int WSZ = D_MODEL * D_MODEL;
    dim3 wgrid(16, 16);
    prep_w<<<wgrid, 256>>>(Wq, WTh + 0 * WSZ, WTl + 0 * WSZ);
    prep_w<<<wgrid, 256>>>(Wk, WTh + 1 * WSZ, WTl + 1 * WSZ);
    prep_w<<<wgrid, 256>>>(Wv, WTh + 2 * WSZ, WTl + 2 * WSZ);
    prep_w<<<wgrid, 256>>>(Wo, WTh + 3 * WSZ, WTl + 3 * WSZ);
    prep_split<<<NNODES * D_MODEL / 1024, 256>>>(x, Xh, Xl);

    dim3 ggrid(D_MODEL / 128, NNODES / 128);  // (4, 64)
    gemm_mma<<<ggrid, 256>>>(Xh, Xl, WTh + 0 * WSZ, WTl + 0 * WSZ, bq, Qp);
    gemm_mma<<<ggrid, 256>>>(Xh, Xl, WTh + 1 * WSZ, WTl + 1 * WSZ, bk, Kp);
    gemm_mma<<<ggrid, 256>>>(Xh, Xl, WTh + 2 * WSZ, WTl + 2 * WSZ, bv, Vp);

    edge_mlp_kernel<<<NEDGES / 1024, 256>>>(ea, W1, b1, W2, b2, EBp);

    attn_kernel<<<NGRAPHS * NHEADS, 128, attn_smem>>>(eidx);

    prep_split<<<NNODES * D_MODEL / 1024, 256>>>(Op, Oh, Ol);
    gemm_mma<<<ggrid, 256>>>(Oh, Ol, WTh + 3 * WSZ, WTl + 3 * WSZ, bo, out);
}

// round 8
// speedup vs baseline: 1.6506x; 1.1516x over previous
#include <cuda_runtime.h>
#include <cuda_bf16.h>
#include <cstdint>

#define D_MODEL 512
#define NHEADS  8
#define DK      64
#define NG      128
#define NGRAPHS 64
#define NNODES  8192
#define EPG     4096
#define NEDGES  262144
#define KPAD    40
#define NSZ     (NNODES * D_MODEL)
#define WSZ     (D_MODEL * D_MODEL)

// ---------------- scratch (static device allocations) ----------------------
__device__ float g_QKV[3 * NSZ];
__device__ float g_O  [NSZ];
__device__ float g_EB [NEDGES * NHEADS];

__device__ __nv_bfloat16 g_Xhi[NSZ];
__device__ __nv_bfloat16 g_Xlo[NSZ];
__device__ __nv_bfloat16 g_Ohi[NSZ];
__device__ __nv_bfloat16 g_Olo[NSZ];
__device__ __nv_bfloat16 g_WThi[4 * WSZ];   // [n][k] transposed
__device__ __nv_bfloat16 g_WTlo[4 * WSZ];

// ---------------- helpers ---------------------------------------------------
__device__ __forceinline__ uint32_t smem_u32(const void* p) {
    uint32_t a;
    asm("{ .reg .u64 t; cvta.to.shared.u64 t, %1; cvt.u32.u64 %0, t; }" : "=r"(a) : "l"(p));
    return a;
}
__device__ __forceinline__ void split_bf16(float v, __nv_bfloat16& hi, __nv_bfloat16& lo) {
    hi = __float2bfloat16(v);
    lo = __float2bfloat16(v - __bfloat162float(hi));
}
__device__ __forceinline__ uint32_t pack_bf16x2(float lo_elem, float hi_elem) {
    uint32_t r;
    asm("cvt.rn.bf16x2.f32 %0, %1, %2;" : "=r"(r) : "f"(hi_elem), "f"(lo_elem));
    return r;
}
__device__ __forceinline__ void mma16816(float* d, const uint32_t* a, uint32_t b0, uint32_t b1) {
    asm volatile(
        "mma.sync.aligned.m16n8k16.row.col.f32.bf16.bf16.f32 "
        "{%0,%1,%2,%3}, {%4,%5,%6,%7}, {%8,%9}, {%0,%1,%2,%3};"
        : "+f"(d[0]), "+f"(d[1]), "+f"(d[2]), "+f"(d[3])
        : "r"(a[0]), "r"(a[1]), "r"(a[2]), "r"(a[3]), "r"(b0), "r"(b1));
}

#define CP16(dst, src) asm volatile("cp.async.cg.shared.global [%0], [%1], 16;" :: "r"(dst), "l"(src))
#define CPCOMMIT()     asm volatile("cp.async.commit_group;")
#define CPWAIT1()      asm volatile("cp.async.wait_group 1;")
#define CPWAIT0()      asm volatile("cp.async.wait_group 0;")
#define LDSM4(R0,R1,R2,R3,A) \
    asm volatile("ldmatrix.sync.aligned.m8n8.x4.shared.b16 {%0,%1,%2,%3}, [%4];" \
                 : "=r"(R0), "=r"(R1), "=r"(R2), "=r"(R3) : "r"(A))

// ---------------- prep: elementwise hi/lo split ------------------------------
__global__ __launch_bounds__(256)
void prep_split(const float* __restrict__ X, __nv_bfloat16* __restrict__ hi,
                __nv_bfloat16* __restrict__ lo) {
    int i = (blockIdx.x * 256 + threadIdx.x) * 4;
    float4 v = *(const float4*)(X + i);
    __nv_bfloat16 h[4], l[4];
    split_bf16(v.x, h[0], l[0]);
    split_bf16(v.y, h[1], l[1]);
    split_bf16(v.z, h[2], l[2]);
    split_bf16(v.w, h[3], l[3]);
    *(uint2*)(hi + i) = *(uint2*)h;
    *(uint2*)(lo + i) = *(uint2*)l;
}

// ---------------- prep: 4 weights transpose + split, z selects --------------
__global__ __launch_bounds__(256)
void prep_w4(const float* __restrict__ W0, const float* __restrict__ W1p,
             const float* __restrict__ W2p, const float* __restrict__ W3,
             __nv_bfloat16* __restrict__ Thi, __nv_bfloat16* __restrict__ Tlo) {
    __shared__ float tile[32][33];
    const int z = blockIdx.z;
    const float* W = (z == 0) ? W0 : (z == 1) ? W1p : (z == 2) ? W2p : W3;
    __nv_bfloat16* Th = Thi + (size_t)z * WSZ;
    __nv_bfloat16* Tl = Tlo + (size_t)z * WSZ;
    const int k0 = blockIdx.y * 32, n0 = blockIdx.x * 32;
    const int tx = threadIdx.x & 31, ty = threadIdx.x >> 5;
    #pragma unroll
    for (int r = ty; r < 32; r += 8)
        tile[r][tx] = W[(size_t)(k0 + r) * D_MODEL + n0 + tx];
    __syncthreads();
    #pragma unroll
    for (int r = ty; r < 32; r += 8) {
        float v = tile[tx][r];
        __nv_bfloat16 h, l;
        split_bf16(v, h, l);
        size_t o = (size_t)(n0 + r) * D_MODEL + k0 + tx;
        Th[o] = h;
        Tl[o] = l;
    }
}

// ---------------- bf16x3 mma GEMM, ldmatrix + cp.async double-buffer ---------
// CTA 128x128, BK=32, 256 thr (8 warps 4m x 2n), warp 32x64. z selects B/bias/C.
__global__ __launch_bounds__(256, 2)
void gemm_mma(const __nv_bfloat16* __restrict__ Ahi, const __nv_bfloat16* __restrict__ Alo,
              const __nv_bfloat16* __restrict__ WTh, const __nv_bfloat16* __restrict__ WTl,
              const float* __restrict__ bz0, const float* __restrict__ bz1,
              const float* __restrict__ bz2, float* __restrict__ Cbase) {
    extern __shared__ char smc[];
    const uint32_t smb = smem_u32(smc);
    const uint32_t STG = 40960;   // per-stage: Ah 0 | Al 10240 | Bh 20480 | Bl 30720

    const int z = blockIdx.z;
    const __nv_bfloat16* Bhi = WTh + (size_t)z * WSZ;
    const __nv_bfloat16* Blo = WTl + (size_t)z * WSZ;
    const float* bias = (z == 0) ? bz0 : (z == 1) ? bz1 : bz2;
    float* C = Cbase + (size_t)z * NSZ;

    const int tid = threadIdx.x, lane = tid & 31, wid = tid >> 5;
    const int wm = (wid & 3) * 32, wn = (wid >> 2) * 64;
    const int bn = blockIdx.x * 128, bm = blockIdx.y * 128;
    const int grp = lane >> 2, th = lane & 3;

    // cp.async mapping: 2 row passes x 4 arrays, 16B each
    const int lr  = tid >> 2;            // 0..63
    const int lcb = (tid & 3) * 16;      // byte offset in 64B k-chunk

    // ldmatrix lane offsets (bytes, within array, before ks)
    const int l07 = lane & 7, q = lane >> 3;
    const uint32_t aOff = (uint32_t)(((wm + l07 + (q & 1) * 8) * KPAD + (q >> 1) * 8) * 2);
    const uint32_t bOff = (uint32_t)(((wn + l07 + (q >> 1) * 8) * KPAD + (q & 1) * 8) * 2);

    float acc[2][8][4];
    #pragma unroll
    for (int mi = 0; mi < 2; mi++)
        #pragma unroll
        for (int ni = 0; ni < 8; ni++)
            #pragma unroll
            for (int j = 0; j < 4; j++) acc[mi][ni][j] = 0.f;

#define LOADSTAGE(s, k0) do {                                                            \
    uint32_t sb_ = smb + (uint32_t)(s) * STG;                                            \
    _Pragma("unroll")                                                                    \
    for (int p_ = 0; p_ < 2; p_++) {                                                     \
        int r_ = p_ * 64 + lr;                                                           \
        uint32_t d_ = sb_ + (uint32_t)(r_ * 80 + lcb);                                   \
        CP16(d_,         (const char*)(Ahi + (size_t)(bm + r_) * D_MODEL + (k0)) + lcb); \
        CP16(d_ + 10240, (const char*)(Alo + (size_t)(bm + r_) * D_MODEL + (k0)) + lcb); \
        CP16(d_ + 20480, (const char*)(Bhi + (size_t)(bn + r_) * D_MODEL + (k0)) + lcb); \
        CP16(d_ + 30720, (const char*)(Blo + (size_t)(bn + r_) * D_MODEL + (k0)) + lcb); \
    }                                                                                    \
} while (0)

    LOADSTAGE(0, 0);
    CPCOMMIT();

    #pragma unroll 1
    for (int it = 0; it < 16; it++) {
        if (it < 15) {
            LOADSTAGE((it + 1) & 1, (it + 1) * 32);
            CPCOMMIT();
            CPWAIT1();
        } else {
            CPWAIT0();
        }
        __syncthreads();

        const uint32_t stb = smb + (uint32_t)(it & 1) * STG;
        #pragma unroll
        for (int ks = 0; ks < 32; ks += 16) {
            uint32_t ah[2][4], al[2][4];
            uint32_t aAdr = stb + aOff + ks * 2;
            LDSM4(ah[0][0], ah[0][1], ah[0][2], ah[0][3], aAdr);
            LDSM4(ah[1][0], ah[1][1], ah[1][2], ah[1][3], aAdr + 1280);
            LDSM4(al[0][0], al[0][1], al[0][2], al[0][3], aAdr + 10240);
            LDSM4(al[1][0], al[1][1], al[1][2], al[1][3], aAdr + 10240 + 1280);

            #pragma unroll
            for (int nip = 0; nip < 4; nip++) {
                uint32_t bAdr = stb + 20480 + bOff + ks * 2 + nip * 1280;
                uint32_t h0, h1, h2, h3, u0, u1, u2, u3;
                LDSM4(h0, h1, h2, h3, bAdr);            // hi: ni even (b0,b1), ni odd (b0,b1)
                LDSM4(u0, u1, u2, u3, bAdr + 10240);    // lo
                const int ni = nip * 2;
                #pragma unroll
                for (int mi = 0; mi < 2; mi++) {
                    mma16816(acc[mi][ni], ah[mi], h0, h1);
                    mma16816(acc[mi][ni], ah[mi], u0, u1);
                    mma16816(acc[mi][ni], al[mi], h0, h1);
                    mma16816(acc[mi][ni + 1], ah[mi], h2, h3);
                    mma16816(acc[mi][ni + 1], ah[mi], u2, u3);
                    mma16816(acc[mi][ni + 1], al[mi], h2, h3);
                }
            }
        }
        __syncthreads();
    }
#undef LOADSTAGE

    #pragma unroll
    for (int mi = 0; mi < 2; mi++) {
        int row = bm + wm + mi * 16 + grp;
        #pragma unroll
        for (int ni = 0; ni < 8; ni++) {
            int col = bn + wn + ni * 8 + th * 2;
            float bx = bias[col], by = bias[col + 1];
            *(float2*)&C[(size_t)row * D_MODEL + col] =
                make_float2(acc[mi][ni][0] + bx, acc[mi][ni][1] + by);
            *(float2*)&C[(size_t)(row + 8) * D_MODEL + col] =
                make_float2(acc[mi][ni][2] + bx, acc[mi][ni][3] + by);
        }
    }
}

// ---------------- edge MLP on tensor cores (single-pass bf16) ----------------
// per warp: 16 edges. mma1: ea[16x4 pad16] @ W1-chunk[4x8] -> h; relu;
// accumulator frags repacked directly as A-frags of mma2 (h[16x16] @ W2[16x8]).
__global__ __launch_bounds__(256)
void edge_mlp_mma(const float* __restrict__ ea,
                  const float* __restrict__ W1, const float* __restrict__ b1,
                  const float* __restrict__ W2, const float* __restrict__ b2,
                  float* __restrict__ eb) {
    __shared__ __nv_bfloat16 w1s[D_MODEL * 4];   // [j][c]
    __shared__ __nv_bfloat16 w2t[8 * D_MODEL];   // [h][j]
    __shared__ float b1s[D_MODEL];

    const int tid = threadIdx.x;
    for (int j = tid; j < D_MODEL; j += 256) {
        b1s[j] = b1[j];
        #pragma unroll
        for (int c = 0; c < 4; c++) w1s[j * 4 + c] = __float2bfloat16(W1[c * D_MODEL + j]);
        #pragma unroll
        for (int h = 0; h < 8; h++) w2t[h * D_MODEL + j] = __float2bfloat16(W2[j * 8 + h]);
    }
    __syncthreads();

    const int lane = tid & 31, wid = tid >> 5;
    const int grp = lane >> 2, th = lane & 3;
    const int e0 = blockIdx.x * 128 + wid * 16;

    // A-frag for mma1: cols 0..3 = ea, rest 0 (th<2 holds cols 2th,2th+1)
    uint32_t ea_a[4] = {0u, 0u, 0u, 0u};
    if (th < 2) {
        float2 v0 = *(const float2*)(ea + (size_t)(e0 + grp) * 4 + th * 2);
        float2 v1 = *(const float2*)(ea + (size_t)(e0 + grp + 8) * 4 + th * 2);
        ea_a[0] = pack_bf16x2(v0.x, v0.y);
        ea_a[1] = pack_bf16x2(v1.x, v1.y);
    }

    float acc[4];
    acc[0] = b2[2 * th];
    acc[1] = b2[2 * th + 1];
    acc[2] = acc[0];
    acc[3] = acc[1];

    #pragma unroll 4
    for (int jj = 0; jj < D_MODEL; jj += 16) {
        uint32_t ha[4];
        #pragma unroll
        for (int half = 0; half < 2; half++) {
            const int j0 = jj + half * 8;
            uint32_t w1f = (th < 2) ? *(const uint32_t*)&w1s[(j0 + grp) * 4 + th * 2] : 0u;
            float c[4] = {0.f, 0.f, 0.f, 0.f};
            mma16816(c, ea_a, w1f, 0u);
            float bb0 = b1s[j0 + 2 * th], bb1 = b1s[j0 + 2 * th + 1];
            c[0] = fmaxf(c[0] + bb0, 0.f);
            c[1] = fmaxf(c[1] + bb1, 0.f);
            c[2] = fmaxf(c[2] + bb0, 0.f);
            c[3] = fmaxf(c[3] + bb1, 0.f);
            ha[half * 2 + 0] = pack_bf16x2(c[0], c[1]);
            ha[half * 2 + 1] = pack_bf16x2(c[2], c[3]);
        }
        uint32_t w2f0 = *(const uint32_t*)&w2t[grp * D_MODEL + jj + th * 2];
        uint32_t w2f1 = *(const uint32_t*)&w2t[grp * D_MODEL + jj + 8 + th * 2];
        mma16816(acc, ha, w2f0, w2f1);
    }

    *(float2*)(eb + (size_t)(e0 + grp) * 8 + 2 * th)     = make_float2(acc[0], acc[1]);
    *(float2*)(eb + (size_t)(e0 + grp + 8) * 8 + 2 * th) = make_float2(acc[2], acc[3]);
}

// ---------------- fused block-diagonal attention -----------------------------
__global__ __launch_bounds__(128)
void attn_kernel(const int* __restrict__ edge_index) {
    extern __shared__ float smf[];
    float* Kt = smf;
    float* Vt = smf + NG * DK;
    float* S  = smf + 2 * NG * DK;   // [128][129]

    const int g = blockIdx.x >> 3;
    const int h = blockIdx.x & 7;
    const int tid = threadIdx.x;

    const float* Kg = g_QKV + NSZ     + (size_t)g * NG * D_MODEL + h * DK;
    const float* Vg = g_QKV + 2 * NSZ + (size_t)g * NG * D_MODEL + h * DK;

    for (int idx = tid; idx < NG * DK / 4; idx += 128) {
        int row = idx >> 4;
        int c4  = idx & 15;
        ((float4*)Kt)[row * 16 + c4] = *(const float4*)(Kg + (size_t)row * D_MODEL + c4 * 4);
        ((float4*)Vt)[row * 16 + c4] = *(const float4*)(Vg + (size_t)row * D_MODEL + c4 * 4);
    }

    float q[DK];
    const float* Qg = g_QKV + (size_t)(g * NG + tid) * D_MODEL + h * DK;
    #pragma unroll
    for (int d = 0; d < DK; d += 4) {
        float4 v = *(const float4*)(Qg + d);
        q[d] = v.x; q[d + 1] = v.y; q[d + 2] = v.z; q[d + 3] = v.w;
    }
    __syncthreads();

    const float scale = 0.125f;
    for (int j = 0; j < NG; j++) {
        float s0 = 0.f, s1 = 0.f, s2 = 0.f, s3 = 0.f;
        #pragma unroll
        for (int d = 0; d < DK; d += 4) {
            float4 kv = *(const float4*)(Kt + j * DK + d);
            s0 = fmaf(q[d],     kv.x, s0);
            s1 = fmaf(q[d + 1], kv.y, s1);
            s2 = fmaf(q[d + 2], kv.z, s2);
            s3 = fmaf(q[d + 3], kv.w, s3);
        }
        S[tid * 129 + j] = ((s0 + s1) + (s2 + s3)) * scale;
    }
    __syncthreads();

    const int* srcp = edge_index;
    const int* dstp = edge_index + NEDGES;
    for (int t = tid; t < EPG; t += 128) {
        int e  = g * EPG + t;
        int ls = srcp[e] & (NG - 1);
        int ld = dstp[e] & (NG - 1);
        atomicAdd(&S[ls * 129 + ld], g_EB[(size_t)e * 8 + h]);
    }
    __syncthreads();

    float m = -1e30f;
    for (int j = 0; j < NG; j++) m = fmaxf(m, S[tid * 129 + j]);
    float sum = 0.f;
    for (int j = 0; j < NG; j++) {
        float p = __expf(S[tid * 129 + j] - m);
        S[tid * 129 + j] = p;
        sum += p;
    }
    float inv = 1.f / sum;

    float acc[DK];
    #pragma unroll
    for (int d = 0; d < DK; d++) acc[d] = 0.f;
    for (int j = 0; j < NG; j++) {
        float p = S[tid * 129 + j];
        #pragma unroll
        for (int d = 0; d < DK; d += 4) {
            float4 v = *(const float4*)(Vt + j * DK + d);
            acc[d]     = fmaf(p, v.x, acc[d]);
            acc[d + 1] = fmaf(p, v.y, acc[d + 1]);
            acc[d + 2] = fmaf(p, v.z, acc[d + 2]);
            acc[d + 3] = fmaf(p, v.w, acc[d + 3]);
        }
    }

    float* Og = g_O + (size_t)(g * NG + tid) * D_MODEL + h * DK;
    #pragma unroll
    for (int d = 0; d < DK; d += 4) {
        float4 o;
        o.x = acc[d] * inv; o.y = acc[d + 1] * inv;
        o.z = acc[d + 2] * inv; o.w = acc[d + 3] * inv;
        *(float4*)(Og + d) = o;
    }
}

// ---------------- launcher ---------------------------------------------------
extern "C" void kernel_launch(void* const* d_in, const int* in_sizes, int n_in,
                              void* d_out, int out_size) {
    const float* x    = (const float*)d_in[0];
    const int*   eidx = (const int*)  d_in[1];
    const float* ea   = (const float*)d_in[2];
    const float* Wq = (const float*)d_in[5];
    const float* bq = (const float*)d_in[6];
    const float* Wk = (const float*)d_in[7];
    const float* bk = (const float*)d_in[8];
    const float* Wv = (const float*)d_in[9];
    const float* bv = (const float*)d_in[10];
    const float* Wo = (const float*)d_in[11];
    const float* bo = (const float*)d_in[12];
    const float* W1 = (const float*)d_in[13];
    const float* b1 = (const float*)d_in[14];
    const float* W2 = (const float*)d_in[15];
    const float* b2 = (const float*)d_in[16];
    float* out = (float*)d_out;

    float *QKVp, *Op, *EBp;
    __nv_bfloat16 *Xh, *Xl, *Oh, *Ol, *WTh, *WTl;
    cudaGetSymbolAddress((void**)&QKVp, g_QKV);
    cudaGetSymbolAddress((void**)&Op,   g_O);
    cudaGetSymbolAddress((void**)&EBp,  g_EB);
    cudaGetSymbolAddress((void**)&Xh,   g_Xhi);
    cudaGetSymbolAddress((void**)&Xl,   g_Xlo);
    cudaGetSymbolAddress((void**)&Oh,   g_Ohi);
    cudaGetSymbolAddress((void**)&Ol,   g_Olo);
    cudaGetSymbolAddress((void**)&WTh,  g_WThi);
    cudaGetSymbolAddress((void**)&WTl,  g_WTlo);

    const int gemm_smem = 2 * 40960;   // 81920
    cudaFuncSetAttribute(gemm_mma, cudaFuncAttributeMaxDynamicSharedMemorySize, gemm_smem);
    const int attn_smem = (2 * NG * DK + NG * 129) * (int)sizeof(float);
    cudaFuncSetAttribute(attn_kernel, cudaFuncAttributeMaxDynamicSharedMemorySize, attn_smem);

    prep_w4<<<dim3(16, 16, 4), 256>>>(Wq, Wk, Wv, Wo, WTh, WTl);
    prep_split<<<NSZ / 1024, 256>>>(x, Xh, Xl);

    // fused QKV: z = 0,1,2
    gemm_mma<<<dim3(4, 64, 3), 256, gemm_smem>>>(Xh, Xl, WTh, WTl, bq, bk, bv, QKVp);

    edge_mlp_mma<<<NEDGES / 128, 256>>>(ea, W1, b1, W2, b2, EBp);

    attn_kernel<<<NGRAPHS * NHEADS, 128, attn_smem>>>(eidx);

    prep_split<<<NSZ / 1024, 256>>>(Op, Oh, Ol);
    // O projection: weights at index 3, single z
    gemm_mma<<<dim3(4, 64, 1), 256, gemm_smem>>>(Oh, Ol, WTh + 3 * WSZ, WTl + 3 * WSZ,
                                                 bo, bo, bo, out);
}

// round 9
// speedup vs baseline: 1.7771x; 1.0766x over previous
#include <cuda_runtime.h>
#include <cuda_bf16.h>
#include <cstdint>

#define D_MODEL 512
#define NHEADS  8
#define DK      64
#define NG      128
#define NGRAPHS 64
#define NNODES  8192
#define EPG     4096
#define NEDGES  262144
#define KPAD    40
#define W2PAD   520
#define NSZ     (NNODES * D_MODEL)
#define WSZ     (D_MODEL * D_MODEL)

// ---------------- scratch (static device allocations) ----------------------
__device__ float g_QKV[3 * NSZ];
__device__ float g_EB [NEDGES * NHEADS];

__device__ __nv_bfloat16 g_Xhi[NSZ];
__device__ __nv_bfloat16 g_Xlo[NSZ];
__device__ __nv_bfloat16 g_Ohi[NSZ];
__device__ __nv_bfloat16 g_Olo[NSZ];
__device__ __nv_bfloat16 g_WThi[4 * WSZ];   // [n][k] transposed
__device__ __nv_bfloat16 g_WTlo[4 * WSZ];

// ---------------- helpers ---------------------------------------------------
__device__ __forceinline__ uint32_t smem_u32(const void* p) {
    uint32_t a;
    asm("{ .reg .u64 t; cvta.to.shared.u64 t, %1; cvt.u32.u64 %0, t; }" : "=r"(a) : "l"(p));
    return a;
}
__device__ __forceinline__ void split_bf16(float v, __nv_bfloat16& hi, __nv_bfloat16& lo) {
    hi = __float2bfloat16(v);
    lo = __float2bfloat16(v - __bfloat162float(hi));
}
__device__ __forceinline__ uint32_t pack_bf16x2(float lo_elem, float hi_elem) {
    uint32_t r;
    asm("cvt.rn.bf16x2.f32 %0, %1, %2;" : "=r"(r) : "f"(hi_elem), "f"(lo_elem));
    return r;
}
__device__ __forceinline__ void mma16816(float* d, const uint32_t* a, uint32_t b0, uint32_t b1) {
    asm volatile(
        "mma.sync.aligned.m16n8k16.row.col.f32.bf16.bf16.f32 "
        "{%0,%1,%2,%3}, {%4,%5,%6,%7}, {%8,%9}, {%0,%1,%2,%3};"
        : "+f"(d[0]), "+f"(d[1]), "+f"(d[2]), "+f"(d[3])
        : "r"(a[0]), "r"(a[1]), "r"(a[2]), "r"(a[3]), "r"(b0), "r"(b1));
}

#define CP16(dst, src) asm volatile("cp.async.cg.shared.global [%0], [%1], 16;" :: "r"(dst), "l"(src))
#define CPCOMMIT()     asm volatile("cp.async.commit_group;")
#define CPWAIT1()      asm volatile("cp.async.wait_group 1;")
#define CPWAIT0()      asm volatile("cp.async.wait_group 0;")
#define LDSM4(R0,R1,R2,R3,A) \
    asm volatile("ldmatrix.sync.aligned.m8n8.x4.shared.b16 {%0,%1,%2,%3}, [%4];" \
                 : "=r"(R0), "=r"(R1), "=r"(R2), "=r"(R3) : "r"(A))

// ---------------- prep: elementwise hi/lo split ------------------------------
__global__ __launch_bounds__(256)
void prep_split(const float* __restrict__ X, __nv_bfloat16* __restrict__ hi,
                __nv_bfloat16* __restrict__ lo) {
    int i = (blockIdx.x * 256 + threadIdx.x) * 4;
    float4 v = *(const float4*)(X + i);
    __nv_bfloat16 h[4], l[4];
    split_bf16(v.x, h[0], l[0]);
    split_bf16(v.y, h[1], l[1]);
    split_bf16(v.z, h[2], l[2]);
    split_bf16(v.w, h[3], l[3]);
    *(uint2*)(hi + i) = *(uint2*)h;
    *(uint2*)(lo + i) = *(uint2*)l;
}

// ---------------- prep: 4 weights transpose + split, z selects --------------
__global__ __launch_bounds__(256)
void prep_w4(const float* __restrict__ W0, const float* __restrict__ W1p,
             const float* __restrict__ W2p, const float* __restrict__ W3,
             __nv_bfloat16* __restrict__ Thi, __nv_bfloat16* __restrict__ Tlo) {
    __shared__ float tile[32][33];
    const int z = blockIdx.z;
    const float* W = (z == 0) ? W0 : (z == 1) ? W1p : (z == 2) ? W2p : W3;
    __nv_bfloat16* Th = Thi + (size_t)z * WSZ;
    __nv_bfloat16* Tl = Tlo + (size_t)z * WSZ;
    const int k0 = blockIdx.y * 32, n0 = blockIdx.x * 32;
    const int tx = threadIdx.x & 31, ty = threadIdx.x >> 5;
    #pragma unroll
    for (int r = ty; r < 32; r += 8)
        tile[r][tx] = W[(size_t)(k0 + r) * D_MODEL + n0 + tx];
    __syncthreads();
    #pragma unroll
    for (int r = ty; r < 32; r += 8) {
        float v = tile[tx][r];
        __nv_bfloat16 h, l;
        split_bf16(v, h, l);
        size_t o = (size_t)(n0 + r) * D_MODEL + k0 + tx;
        Th[o] = h;
        Tl[o] = l;
    }
}

// ---------------- bf16x3 mma GEMM, term-major mma ordering -------------------
// CTA 128x128, BK=32, 256 thr (8 warps 4m x 2n), warp 32x64. z selects B/bias/C.
__global__ __launch_bounds__(256, 2)
void gemm_mma(const __nv_bfloat16* __restrict__ Ahi, const __nv_bfloat16* __restrict__ Alo,
              const __nv_bfloat16* __restrict__ WTh, const __nv_bfloat16* __restrict__ WTl,
              const float* __restrict__ bz0, const float* __restrict__ bz1,
              const float* __restrict__ bz2, float* __restrict__ Cbase) {
    extern __shared__ char smc[];
    const uint32_t smb = smem_u32(smc);
    const uint32_t STG = 40960;   // per-stage: Ah 0 | Al 10240 | Bh 20480 | Bl 30720

    const int z = blockIdx.z;
    const __nv_bfloat16* Bhi = WTh + (size_t)z * WSZ;
    const __nv_bfloat16* Blo = WTl + (size_t)z * WSZ;
    const float* bias = (z == 0) ? bz0 : (z == 1) ? bz1 : bz2;
    float* C = Cbase + (size_t)z * NSZ;

    const int tid = threadIdx.x, lane = tid & 31, wid = tid >> 5;
    const int wm = (wid & 3) * 32, wn = (wid >> 2) * 64;
    const int bn = blockIdx.x * 128, bm = blockIdx.y * 128;
    const int grp = lane >> 2, th = lane & 3;

    const int lr  = tid >> 2;            // 0..63
    const int lcb = (tid & 3) * 16;      // byte offset in 64B k-chunk

    const int l07 = lane & 7, q = lane >> 3;
    const uint32_t aOff = (uint32_t)(((wm + l07 + (q & 1) * 8) * KPAD + (q >> 1) * 8) * 2);
    const uint32_t bOff = (uint32_t)(((wn + l07 + (q >> 1) * 8) * KPAD + (q & 1) * 8) * 2);

    float acc[2][8][4];
    #pragma unroll
    for (int mi = 0; mi < 2; mi++)
        #pragma unroll
        for (int ni = 0; ni < 8; ni++)
            #pragma unroll
            for (int j = 0; j < 4; j++) acc[mi][ni][j] = 0.f;

#define LOADSTAGE(s, k0) do {                                                            \
    uint32_t sb_ = smb + (uint32_t)(s) * STG;                                            \
    _Pragma("unroll")                                                                    \
    for (int p_ = 0; p_ < 2; p_++) {                                                     \
        int r_ = p_ * 64 + lr;                                                           \
        uint32_t d_ = sb_ + (uint32_t)(r_ * 80 + lcb);                                   \
        CP16(d_,         (const char*)(Ahi + (size_t)(bm + r_) * D_MODEL + (k0)) + lcb); \
        CP16(d_ + 10240, (const char*)(Alo + (size_t)(bm + r_) * D_MODEL + (k0)) + lcb); \
        CP16(d_ + 20480, (const char*)(Bhi + (size_t)(bn + r_) * D_MODEL + (k0)) + lcb); \
        CP16(d_ + 30720, (const char*)(Blo + (size_t)(bn + r_) * D_MODEL + (k0)) + lcb); \
    }                                                                                    \
} while (0)

    LOADSTAGE(0, 0);
    CPCOMMIT();

    #pragma unroll 1
    for (int it = 0; it < 16; it++) {
        if (it < 15) {
            LOADSTAGE((it + 1) & 1, (it + 1) * 32);
            CPCOMMIT();
            CPWAIT1();
        } else {
            CPWAIT0();
        }
        __syncthreads();

        const uint32_t stb = smb + (uint32_t)(it & 1) * STG;
        #pragma unroll
        for (int ks = 0; ks < 32; ks += 16) {
            uint32_t ah[2][4], al[2][4];
            uint32_t aAdr = stb + aOff + ks * 2;
            LDSM4(ah[0][0], ah[0][1], ah[0][2], ah[0][3], aAdr);
            LDSM4(ah[1][0], ah[1][1], ah[1][2], ah[1][3], aAdr + 1280);
            LDSM4(al[0][0], al[0][1], al[0][2], al[0][3], aAdr + 10240);
            LDSM4(al[1][0], al[1][1], al[1][2], al[1][3], aAdr + 11520);

            #pragma unroll
            for (int half = 0; half < 2; half++) {
                uint32_t bh[2][4], bu[2][4];
                #pragma unroll
                for (int p = 0; p < 2; p++) {
                    uint32_t bAdr = stb + 20480 + bOff + ks * 2 + (half * 2 + p) * 1280;
                    LDSM4(bh[p][0], bh[p][1], bh[p][2], bh[p][3], bAdr);
                    LDSM4(bu[p][0], bu[p][1], bu[p][2], bu[p][3], bAdr + 10240);
                }
                // term-major: hi*hi, then hi*lo, then lo*hi (acc reuse distance 8)
                #pragma unroll
                for (int p = 0; p < 2; p++)
                    #pragma unroll
                    for (int mi = 0; mi < 2; mi++) {
                        const int ni = half * 4 + p * 2;
                        mma16816(acc[mi][ni],     ah[mi], bh[p][0], bh[p][1]);
                        mma16816(acc[mi][ni + 1], ah[mi], bh[p][2], bh[p][3]);
                    }
                #pragma unroll
                for (int p = 0; p < 2; p++)
                    #pragma unroll
                    for (int mi = 0; mi < 2; mi++) {
                        const int ni = half * 4 + p * 2;
                        mma16816(acc[mi][ni],     ah[mi], bu[p][0], bu[p][1]);
                        mma16816(acc[mi][ni + 1], ah[mi], bu[p][2], bu[p][3]);
                    }
                #pragma unroll
                for (int p = 0; p < 2; p++)
                    #pragma unroll
                    for (int mi = 0; mi < 2; mi++) {
                        const int ni = half * 4 + p * 2;
                        mma16816(acc[mi][ni],     al[mi], bh[p][0], bh[p][1]);
                        mma16816(acc[mi][ni + 1], al[mi], bh[p][2], bh[p][3]);
                    }
            }
        }
        __syncthreads();
    }
#undef LOADSTAGE

    #pragma unroll
    for (int mi = 0; mi < 2; mi++) {
        int row = bm + wm + mi * 16 + grp;
        #pragma unroll
        for (int ni = 0; ni < 8; ni++) {
            int col = bn + wn + ni * 8 + th * 2;
            float bx = bias[col], by = bias[col + 1];
            *(float2*)&C[(size_t)row * D_MODEL + col] =
                make_float2(acc[mi][ni][0] + bx, acc[mi][ni][1] + by);
            *(float2*)&C[(size_t)(row + 8) * D_MODEL + col] =
                make_float2(acc[mi][ni][2] + bx, acc[mi][ni][3] + by);
        }
    }
}

// ---------------- edge MLP on tensor cores: 64 edges/warp --------------------
// b1 folded into mma1 as a 5th input feature (ea col4 = 1.0, W1ext row4 = b1).
__global__ __launch_bounds__(256)
void edge_mlp_mma(const float* __restrict__ ea,
                  const float* __restrict__ W1, const float* __restrict__ b1,
                  const float* __restrict__ W2, const float* __restrict__ b2,
                  float* __restrict__ eb) {
    __shared__ __nv_bfloat16 w1e[D_MODEL * 8];   // [j][0..3]=W1, [4]=b1, [5..7]=0
    __shared__ __nv_bfloat16 w2t[8 * W2PAD];     // [h][j], padded stride

    const int tid = threadIdx.x;
    for (int j = tid; j < D_MODEL; j += 256) {
        #pragma unroll
        for (int c = 0; c < 4; c++) w1e[j * 8 + c] = __float2bfloat16(W1[c * D_MODEL + j]);
        w1e[j * 8 + 4] = __float2bfloat16(b1[j]);
        w1e[j * 8 + 5] = __float2bfloat16(0.f);
        w1e[j * 8 + 6] = __float2bfloat16(0.f);
        w1e[j * 8 + 7] = __float2bfloat16(0.f);
        #pragma unroll
        for (int h = 0; h < 8; h++) w2t[h * W2PAD + j] = __float2bfloat16(W2[j * 8 + h]);
    }
    __syncthreads();

    const int lane = tid & 31, wid = tid >> 5;
    const int grp = lane >> 2, th = lane & 3;
    const int e0 = blockIdx.x * 512 + wid * 64;
    const uint32_t zero = 0;

    uint32_t ea0[4], ea1[4];
    if (th < 2) {
        #pragma unroll
        for (int t = 0; t < 4; t++) {
            float2 v0 = *(const float2*)(ea + (size_t)(e0 + t * 16 + grp) * 4 + th * 2);
            float2 v1 = *(const float2*)(ea + (size_t)(e0 + t * 16 + grp + 8) * 4 + th * 2);
            ea0[t] = pack_bf16x2(v0.x, v0.y);
            ea1[t] = pack_bf16x2(v1.x, v1.y);
        }
    } else if (th == 2) {
        uint32_t one = pack_bf16x2(1.f, 0.f);
        #pragma unroll
        for (int t = 0; t < 4; t++) { ea0[t] = one; ea1[t] = one; }
    } else {
        #pragma unroll
        for (int t = 0; t < 4; t++) { ea0[t] = 0u; ea1[t] = 0u; }
    }

    float acc[4][4];
    {
        float bz0 = b2[2 * th], bz1 = b2[2 * th + 1];
        #pragma unroll
        for (int t = 0; t < 4; t++) {
            acc[t][0] = bz0; acc[t][1] = bz1; acc[t][2] = bz0; acc[t][3] = bz1;
        }
    }

    #pragma unroll 2
    for (int jj = 0; jj < D_MODEL; jj += 16) {
        uint32_t ha[4][4];
        #pragma unroll
        for (int half = 0; half < 2; half++) {
            const int j0 = jj + half * 8;
            uint32_t w1f = *(const uint32_t*)&w1e[(j0 + grp) * 8 + th * 2];
            #pragma unroll
            for (int t = 0; t < 4; t++) {
                float c[4] = {0.f, 0.f, 0.f, 0.f};
                uint32_t av[4] = {ea0[t], ea1[t], zero, zero};
                mma16816(c, av, w1f, zero);
                ha[t][half * 2 + 0] = pack_bf16x2(fmaxf(c[0], 0.f), fmaxf(c[1], 0.f));
                ha[t][half * 2 + 1] = pack_bf16x2(fmaxf(c[2], 0.f), fmaxf(c[3], 0.f));
            }
        }
        uint32_t w2f0 = *(const uint32_t*)&w2t[grp * W2PAD + jj + th * 2];
        uint32_t w2f1 = *(const uint32_t*)&w2t[grp * W2PAD + jj + 8 + th * 2];
        #pragma unroll
        for (int t = 0; t < 4; t++) mma16816(acc[t], ha[t], w2f0, w2f1);
    }

    #pragma unroll
    for (int t = 0; t < 4; t++) {
        *(float2*)(eb + (size_t)(e0 + t * 16 + grp) * 8 + 2 * th) =
            make_float2(acc[t][0], acc[t][1]);
        *(float2*)(eb + (size_t)(e0 + t * 16 + grp + 8) * 8 + 2 * th) =
            make_float2(acc[t][2], acc[t][3]);
    }
}

// ---------------- fused block-diagonal attention -----------------------------
__global__ __launch_bounds__(128)
void attn_kernel(const int* __restrict__ edge_index) {
    extern __shared__ float smf[];
    float* Kt = smf;
    float* Vt = smf + NG * DK;
    float* S  = smf + 2 * NG * DK;   // [128][129]

    const int g = blockIdx.x >> 3;
    const int h = blockIdx.x & 7;
    const int tid = threadIdx.x;

    const float* Kg = g_QKV + NSZ     + (size_t)g * NG * D_MODEL + h * DK;
    const float* Vg = g_QKV + 2 * NSZ + (size_t)g * NG * D_MODEL + h * DK;

    for (int idx = tid; idx < NG * DK / 4; idx += 128) {
        int row = idx >> 4;
        int c4  = idx & 15;
        ((float4*)Kt)[row * 16 + c4] = *(const float4*)(Kg + (size_t)row * D_MODEL + c4 * 4);
        ((float4*)Vt)[row * 16 + c4] = *(const float4*)(Vg + (size_t)row * D_MODEL + c4 * 4);
    }

    float q[DK];
    const float* Qg = g_QKV + (size_t)(g * NG + tid) * D_MODEL + h * DK;
    #pragma unroll
    for (int d = 0; d < DK; d += 4) {
        float4 v = *(const float4*)(Qg + d);
        q[d] = v.x; q[d + 1] = v.y; q[d + 2] = v.z; q[d + 3] = v.w;
    }
    __syncthreads();

    const float scale = 0.125f;
    for (int j = 0; j < NG; j++) {
        float s0 = 0.f, s1 = 0.f, s2 = 0.f, s3 = 0.f;
        #pragma unroll
        for (int d = 0; d < DK; d += 4) {
            float4 kv = *(const float4*)(Kt + j * DK + d);
            s0 = fmaf(q[d],     kv.x, s0);
            s1 = fmaf(q[d + 1], kv.y, s1);
            s2 = fmaf(q[d + 2], kv.z, s2);
            s3 = fmaf(q[d + 3], kv.w, s3);
        }
        S[tid * 129 + j] = ((s0 + s1) + (s2 + s3)) * scale;
    }
    __syncthreads();

    const int* srcp = edge_index;
    const int* dstp = edge_index + NEDGES;
    for (int t = tid; t < EPG; t += 128) {
        int e  = g * EPG + t;
        int ls = srcp[e] & (NG - 1);
        int ld = dstp[e] & (NG - 1);
        atomicAdd(&S[ls * 129 + ld], g_EB[(size_t)e * 8 + h]);
    }
    __syncthreads();

    float m = -1e30f;
    for (int j = 0; j < NG; j++) m = fmaxf(m, S[tid * 129 + j]);
    float sum = 0.f;
    for (int j = 0; j < NG; j++) {
        float p = __expf(S[tid * 129 + j] - m);
        S[tid * 129 + j] = p;
        sum += p;
    }
    float inv = 1.f / sum;

    float acc[DK];
    #pragma unroll
    for (int d = 0; d < DK; d++) acc[d] = 0.f;
    for (int j = 0; j < NG; j++) {
        float p = S[tid * 129 + j];
        #pragma unroll
        for (int d = 0; d < DK; d += 4) {
            float4 v = *(const float4*)(Vt + j * DK + d);
            acc[d]     = fmaf(p, v.x, acc[d]);
            acc[d + 1] = fmaf(p, v.y, acc[d + 1]);
            acc[d + 2] = fmaf(p, v.z, acc[d + 2]);
            acc[d + 3] = fmaf(p, v.w, acc[d + 3]);
        }
    }

    // write bf16 hi/lo directly (feeds O-projection GEMM; kills a prep pass)
    const size_t ob = (size_t)(g * NG + tid) * D_MODEL + h * DK;
    #pragma unroll
    for (int d = 0; d < DK; d += 4) {
        __nv_bfloat16 hv[4], lv[4];
        #pragma unroll
        for (int u = 0; u < 4; u++) split_bf16(acc[d + u] * inv, hv[u], lv[u]);
        *(uint2*)(g_Ohi + ob + d) = *(uint2*)hv;
        *(uint2*)(g_Olo + ob + d) = *(uint2*)lv;
    }
}

// ---------------- launcher ---------------------------------------------------
extern "C" void kernel_launch(void* const* d_in, const int* in_sizes, int n_in,
                              void* d_out, int out_size) {
    const float* x    = (const float*)d_in[0];
    const int*   eidx = (const int*)  d_in[1];
    const float* ea   = (const float*)d_in[2];
    const float* Wq = (const float*)d_in[5];
    const float* bq = (const float*)d_in[6];
    const float* Wk = (const float*)d_in[7];
    const float* bk = (const float*)d_in[8];
    const float* Wv = (const float*)d_in[9];
    const float* bv = (const float*)d_in[10];
    const float* Wo = (const float*)d_in[11];
    const float* bo = (const float*)d_in[12];
    const float* W1 = (const float*)d_in[13];
    const float* b1 = (const float*)d_in[14];
    const float* W2 = (const float*)d_in[15];
    const float* b2 = (const float*)d_in[16];
    float* out = (float*)d_out;

    float *QKVp, *EBp;
    __nv_bfloat16 *Xh, *Xl, *Oh, *Ol, *WTh, *WTl;
    cudaGetSymbolAddress((void**)&QKVp, g_QKV);
    cudaGetSymbolAddress((void**)&EBp,  g_EB);
    cudaGetSymbolAddress((void**)&Xh,   g_Xhi);
    cudaGetSymbolAddress((void**)&Xl,   g_Xlo);
    cudaGetSymbolAddress((void**)&Oh,   g_Ohi);
    cudaGetSymbolAddress((void**)&Ol,   g_Olo);
    cudaGetSymbolAddress((void**)&WTh,  g_WThi);
    cudaGetSymbolAddress((void**)&WTl,  g_WTlo);

    const int gemm_smem = 2 * 40960;   // 81920
    cudaFuncSetAttribute(gemm_mma, cudaFuncAttributeMaxDynamicSharedMemorySize, gemm_smem);
    const int attn_smem = (2 * NG * DK + NG * 129) * (int)sizeof(float);
    cudaFuncSetAttribute(attn_kernel, cudaFuncAttributeMaxDynamicSharedMemorySize, attn_smem);

    prep_w4<<<dim3(16, 16, 4), 256>>>(Wq, Wk, Wv, Wo, WTh, WTl);
    prep_split<<<NSZ / 1024, 256>>>(x, Xh, Xl);

    // fused QKV: z = 0,1,2
    gemm_mma<<<dim3(4, 64, 3), 256, gemm_smem>>>(Xh, Xl, WTh, WTl, bq, bk, bv, QKVp);

    edge_mlp_mma<<<NEDGES / 512, 256>>>(ea, W1, b1, W2, b2, EBp);

    attn_kernel<<<NGRAPHS * NHEADS, 128, attn_smem>>>(eidx);

    // O projection: weights at index 3, single z
    gemm_mma<<<dim3(4, 64, 1), 256, gemm_smem>>>(Oh, Ol, WTh + 3 * WSZ, WTl + 3 * WSZ,
                                                 bo, bo, bo, out);
}

// round 13
// speedup vs baseline: 2.0185x; 1.1358x over previous
#include <cuda_runtime.h>
#include <cuda_bf16.h>
#include <cuda_fp16.h>
#include <cstdint>

#define D_MODEL 512
#define NHEADS  8
#define DK      64
#define NG      128
#define NGRAPHS 64
#define NNODES  8192
#define EPG     4096
#define NEDGES  262144
#define KPAD    40
#define W2PAD   520
#define NSZ     (NNODES * D_MODEL)
#define WSZ     (D_MODEL * D_MODEL)

// ---------------- scratch (static device allocations) ----------------------
__device__ float g_QKV[3 * NSZ];
__device__ float g_EB [NEDGES * NHEADS];

__device__ __half g_Xhi[NSZ];
__device__ __half g_Xlo[NSZ];
__device__ __half g_Ohi[NSZ];
__device__ __half g_Olo[NSZ];
__device__ __half g_WThi[4 * WSZ];   // [n][k] transposed
__device__ __half g_WTlo[4 * WSZ];

// ---------------- helpers ---------------------------------------------------
__device__ __forceinline__ uint32_t smem_u32(const void* p) {
    uint32_t a;
    asm("{ .reg .u64 t; cvta.to.shared.u64 t, %1; cvt.u32.u64 %0, t; }" : "=r"(a) : "l"(p));
    return a;
}
__device__ __forceinline__ void split_h(float v, __half& hi, __half& lo) {
    hi = __float2half_rn(v);
    lo = __float2half_rn(v - __half2float(hi));
}
__device__ __forceinline__ uint32_t pack_bf16x2(float lo_elem, float hi_elem) {
    uint32_t r;
    asm("cvt.rn.bf16x2.f32 %0, %1, %2;" : "=r"(r) : "f"(hi_elem), "f"(lo_elem));
    return r;
}
// fp16 in, fp32 acc
__device__ __forceinline__ void mma16816h(float* d, const uint32_t* a, uint32_t b0, uint32_t b1) {
    asm volatile(
        "mma.sync.aligned.m16n8k16.row.col.f32.f16.f16.f32 "
        "{%0,%1,%2,%3}, {%4,%5,%6,%7}, {%8,%9}, {%0,%1,%2,%3};"
        : "+f"(d[0]), "+f"(d[1]), "+f"(d[2]), "+f"(d[3])
        : "r"(a[0]), "r"(a[1]), "r"(a[2]), "r"(a[3]), "r"(b0), "r"(b1));
}
// bf16 in, fp32 acc (edge MLP)
__device__ __forceinline__ void mma16816(float* d, const uint32_t* a, uint32_t b0, uint32_t b1) {
    asm volatile(
        "mma.sync.aligned.m16n8k16.row.col.f32.bf16.bf16.f32 "
        "{%0,%1,%2,%3}, {%4,%5,%6,%7}, {%8,%9}, {%0,%1,%2,%3};"
        : "+f"(d[0]), "+f"(d[1]), "+f"(d[2]), "+f"(d[3])
        : "r"(a[0]), "r"(a[1]), "r"(a[2]), "r"(a[3]), "r"(b0), "r"(b1));
}

#define CP16(dst, src) asm volatile("cp.async.cg.shared.global [%0], [%1], 16;" :: "r"(dst), "l"(src))
#define CPCOMMIT()     asm volatile("cp.async.commit_group;")
#define CPWAIT1()      asm volatile("cp.async.wait_group 1;")
#define CPWAIT0()      asm volatile("cp.async.wait_group 0;")
#define LDSM4(R0,R1,R2,R3,A) \
    asm volatile("ldmatrix.sync.aligned.m8n8.x4.shared.b16 {%0,%1,%2,%3}, [%4];" \
                 : "=r"(R0), "=r"(R1), "=r"(R2), "=r"(R3) : "r"(A))

// ---------------- prep: elementwise hi/lo split (fp16) -----------------------
__global__ __launch_bounds__(256)
void prep_split(const float* __restrict__ X, __half* __restrict__ hi,
                __half* __restrict__ lo) {
    int i = (blockIdx.x * 256 + threadIdx.x) * 4;
    float4 v = *(const float4*)(X + i);
    __half h[4], l[4];
    split_h(v.x, h[0], l[0]);
    split_h(v.y, h[1], l[1]);
    split_h(v.z, h[2], l[2]);
    split_h(v.w, h[3], l[3]);
    *(uint2*)(hi + i) = *(uint2*)h;
    *(uint2*)(lo + i) = *(uint2*)l;
}

// ---------------- prep: 4 weights transpose + split, z selects --------------
__global__ __launch_bounds__(256)
void prep_w4(const float* __restrict__ W0, const float* __restrict__ W1p,
             const float* __restrict__ W2p, const float* __restrict__ W3,
             __half* __restrict__ Thi, __half* __restrict__ Tlo) {
    __shared__ float tile[32][33];
    const int z = blockIdx.z;
    const float* W = (z == 0) ? W0 : (z == 1) ? W1p : (z == 2) ? W2p : W3;
    __half* Th = Thi + (size_t)z * WSZ;
    __half* Tl = Tlo + (size_t)z * WSZ;
    const int k0 = blockIdx.y * 32, n0 = blockIdx.x * 32;
    const int tx = threadIdx.x & 31, ty = threadIdx.x >> 5;
    #pragma unroll
    for (int r = ty; r < 32; r += 8)
        tile[r][tx] = W[(size_t)(k0 + r) * D_MODEL + n0 + tx];
    __syncthreads();
    #pragma unroll
    for (int r = ty; r < 32; r += 8) {
        float v = tile[tx][r];
        __half h, l;
        split_h(v, h, l);
        size_t o = (size_t)(n0 + r) * D_MODEL + k0 + tx;
        Th[o] = h;
        Tl[o] = l;
    }
}

// ---------------- fp16 mma GEMM, NT=1 (single-pass) or NT=3 (error split) ----
// CTA 128x128, BK=32, 256 thr (8 warps 4m x 2n), warp 32x64. z selects B/bias/C.
template <int NT>
__global__ __launch_bounds__(256, 2)
void gemm_mma(const __half* __restrict__ Ahi, const __half* __restrict__ Alo,
              const __half* __restrict__ WTh, const __half* __restrict__ WTl,
              const float* __restrict__ bz0, const float* __restrict__ bz1,
              const float* __restrict__ bz2, float* __restrict__ Cbase) {
    extern __shared__ char smc[];
    const uint32_t smb = smem_u32(smc);
    const uint32_t STG = (NT == 3) ? 40960u : 20480u;
    const uint32_t OBH = (NT == 3) ? 20480u : 10240u;   // Bhi offset within stage

    const int z = blockIdx.z;
    const __half* Bhi = WTh + (size_t)z * WSZ;
    const __half* Blo = WTl + (size_t)z * WSZ;
    const float* bias = (z == 0) ? bz0 : (z == 1) ? bz1 : bz2;
    float* C = Cbase + (size_t)z * NSZ;

    const int tid = threadIdx.x, lane = tid & 31, wid = tid >> 5;
    const int wm = (wid & 3) * 32, wn = (wid >> 2) * 64;
    const int bn = blockIdx.x * 128, bm = blockIdx.y * 128;
    const int grp = lane >> 2, th = lane & 3;

    const int lr  = tid >> 2;            // 0..63
    const int lcb = (tid & 3) * 16;      // byte offset in 64B k-chunk

    const int l07 = lane & 7, q = lane >> 3;
    const uint32_t aOff = (uint32_t)(((wm + l07 + (q & 1) * 8) * KPAD + (q >> 1) * 8) * 2);
    const uint32_t bOff = (uint32_t)(((wn + l07 + (q >> 1) * 8) * KPAD + (q & 1) * 8) * 2);

    float acc[2][8][4];
    #pragma unroll
    for (int mi = 0; mi < 2; mi++)
        #pragma unroll
        for (int ni = 0; ni < 8; ni++)
            #pragma unroll
            for (int j = 0; j < 4; j++) acc[mi][ni][j] = 0.f;

    auto load_stage = [&](int s, int k0) {
        uint32_t sb = smb + (uint32_t)s * STG;
        #pragma unroll
        for (int p = 0; p < 2; p++) {
            int r = p * 64 + lr;
            uint32_t d = sb + (uint32_t)(r * 80 + lcb);
            CP16(d,       (const char*)(Ahi + (size_t)(bm + r) * D_MODEL + k0) + lcb);
            CP16(d + OBH, (const char*)(Bhi + (size_t)(bn + r) * D_MODEL + k0) + lcb);
            if (NT == 3) {
                CP16(d + 10240, (const char*)(Alo + (size_t)(bm + r) * D_MODEL + k0) + lcb);
                CP16(d + 30720, (const char*)(Blo + (size_t)(bn + r) * D_MODEL + k0) + lcb);
            }
        }
    };

    load_stage(0, 0);
    CPCOMMIT();

    #pragma unroll 1
    for (int it = 0; it < 16; it++) {
        if (it < 15) {
            load_stage((it + 1) & 1, (it + 1) * 32);
            CPCOMMIT();
            CPWAIT1();
        } else {
            CPWAIT0();
        }
        __syncthreads();

        const uint32_t stb = smb + (uint32_t)(it & 1) * STG;
        #pragma unroll
        for (int ks = 0; ks < 32; ks += 16) {
            uint32_t ah[2][4], al[2][4];
            uint32_t aAdr = stb + aOff + ks * 2;
            LDSM4(ah[0][0], ah[0][1], ah[0][2], ah[0][3], aAdr);
            LDSM4(ah[1][0], ah[1][1], ah[1][2], ah[1][3], aAdr + 1280);
            if (NT == 3) {
                LDSM4(al[0][0], al[0][1], al[0][2], al[0][3], aAdr + 10240);
                LDSM4(al[1][0], al[1][1], al[1][2], al[1][3], aAdr + 11520);
            }

            #pragma unroll
            for (int half = 0; half < 2; half++) {
                uint32_t bh[2][4], bu[2][4];
                #pragma unroll
                for (int p = 0; p < 2; p++) {
                    uint32_t bAdr = stb + OBH + bOff + ks * 2 + (half * 2 + p) * 1280;
                    LDSM4(bh[p][0], bh[p][1], bh[p][2], bh[p][3], bAdr);
                    if (NT == 3) LDSM4(bu[p][0], bu[p][1], bu[p][2], bu[p][3], bAdr + 10240);
                }
                #pragma unroll
                for (int p = 0; p < 2; p++)
                    #pragma unroll
                    for (int mi = 0; mi < 2; mi++) {
                        const int ni = half * 4 + p * 2;
                        mma16816h(acc[mi][ni],     ah[mi], bh[p][0], bh[p][1]);
                        mma16816h(acc[mi][ni + 1], ah[mi], bh[p][2], bh[p][3]);
                    }
                if (NT == 3) {
                    #pragma unroll
                    for (int p = 0; p < 2; p++)
                        #pragma unroll
                        for (int mi = 0; mi < 2; mi++) {
                            const int ni = half * 4 + p * 2;
                            mma16816h(acc[mi][ni],     ah[mi], bu[p][0], bu[p][1]);
                            mma16816h(acc[mi][ni + 1], ah[mi], bu[p][2], bu[p][3]);
                        }
                    #pragma unroll
                    for (int p = 0; p < 2; p++)
                        #pragma unroll
                        for (int mi = 0; mi < 2; mi++) {
                            const int ni = half * 4 + p * 2;
                            mma16816h(acc[mi][ni],     al[mi], bh[p][0], bh[p][1]);
                            mma16816h(acc[mi][ni + 1], al[mi], bh[p][2], bh[p][3]);
                        }
                }
            }
        }
        __syncthreads();
    }

    #pragma unroll
    for (int mi = 0; mi < 2; mi++) {
        int row = bm + wm + mi * 16 + grp;
        #pragma unroll
        for (int ni = 0; ni < 8; ni++) {
            int col = bn + wn + ni * 8 + th * 2;
            float bx = bias[col], by = bias[col + 1];
            *(float2*)&C[(size_t)row * D_MODEL + col] =
                make_float2(acc[mi][ni][0] + bx, acc[mi][ni][1] + by);
            *(float2*)&C[(size_t)(row + 8) * D_MODEL + col] =
                make_float2(acc[mi][ni][2] + bx, acc[mi][ni][3] + by);
        }
    }
}

// ---------------- edge MLP on tensor cores: 64 edges/warp --------------------
__global__ __launch_bounds__(256)
void edge_mlp_mma(const float* __restrict__ ea,
                  const float* __restrict__ W1, const float* __restrict__ b1,
                  const float* __restrict__ W2, const float* __restrict__ b2,
                  float* __restrict__ eb) {
    __shared__ __nv_bfloat16 w1e[D_MODEL * 8];   // [j][0..3]=W1, [4]=b1, [5..7]=0
    __shared__ __nv_bfloat16 w2t[8 * W2PAD];     // [h][j], padded stride

    const int tid = threadIdx.x;
    for (int j = tid; j < D_MODEL; j += 256) {
        #pragma unroll
        for (int c = 0; c < 4; c++) w1e[j * 8 + c] = __float2bfloat16(W1[c * D_MODEL + j]);
        w1e[j * 8 + 4] = __float2bfloat16(b1[j]);
        w1e[j * 8 + 5] = __float2bfloat16(0.f);
        w1e[j * 8 + 6] = __float2bfloat16(0.f);
        w1e[j * 8 + 7] = __float2bfloat16(0.f);
        #pragma unroll
        for (int h = 0; h < 8; h++) w2t[h * W2PAD + j] = __float2bfloat16(W2[j * 8 + h]);
    }
    __syncthreads();

    const int lane = tid & 31, wid = tid >> 5;
    const int grp = lane >> 2, th = lane & 3;
    const int e0 = blockIdx.x * 512 + wid * 64;
    const uint32_t zero = 0;

    uint32_t ea0[4], ea1[4];
    if (th < 2) {
        #pragma unroll
        for (int t = 0; t < 4; t++) {
            float2 v0 = *(const float2*)(ea + (size_t)(e0 + t * 16 + grp) * 4 + th * 2);
            float2 v1 = *(const float2*)(ea + (size_t)(e0 + t * 16 + grp + 8) * 4 + th * 2);
            ea0[t] = pack_bf16x2(v0.x, v0.y);
            ea1[t] = pack_bf16x2(v1.x, v1.y);
        }
    } else if (th == 2) {
        uint32_t one = pack_bf16x2(1.f, 0.f);
        #pragma unroll
        for (int t = 0; t < 4; t++) { ea0[t] = one; ea1[t] = one; }
    } else {
        #pragma unroll
        for (int t = 0; t < 4; t++) { ea0[t] = 0u; ea1[t] = 0u; }
    }

    float acc[4][4];
    {
        float bz0 = b2[2 * th], bz1 = b2[2 * th + 1];
        #pragma unroll
        for (int t = 0; t < 4; t++) {
            acc[t][0] = bz0; acc[t][1] = bz1; acc[t][2] = bz0; acc[t][3] = bz1;
        }
    }

    #pragma unroll 2
    for (int jj = 0; jj < D_MODEL; jj += 16) {
        uint32_t ha[4][4];
        #pragma unroll
        for (int half = 0; half < 2; half++) {
            const int j0 = jj + half * 8;
            uint32_t w1f = *(const uint32_t*)&w1e[(j0 + grp) * 8 + th * 2];
            #pragma unroll
            for (int t = 0; t < 4; t++) {
                float c[4] = {0.f, 0.f, 0.f, 0.f};
                uint32_t av[4] = {ea0[t], ea1[t], zero, zero};
                mma16816(c, av, w1f, zero);
                ha[t][half * 2 + 0] = pack_bf16x2(fmaxf(c[0], 0.f), fmaxf(c[1], 0.f));
                ha[t][half * 2 + 1] = pack_bf16x2(fmaxf(c[2], 0.f), fmaxf(c[3], 0.f));
            }
        }
        uint32_t w2f0 = *(const uint32_t*)&w2t[grp * W2PAD + jj + th * 2];
        uint32_t w2f1 = *(const uint32_t*)&w2t[grp * W2PAD + jj + 8 + th * 2];
        #pragma unroll
        for (int t = 0; t < 4; t++) mma16816(acc[t], ha[t], w2f0, w2f1);
    }

    #pragma unroll
    for (int t = 0; t < 4; t++) {
        *(float2*)(eb + (size_t)(e0 + t * 16 + grp) * 8 + 2 * th) =
            make_float2(acc[t][0], acc[t][1]);
        *(float2*)(eb + (size_t)(e0 + t * 16 + grp + 8) * 8 + 2 * th) =
            make_float2(acc[t][2], acc[t][3]);
    }
}

// ---------------- fused block-diagonal attention: 256 thr, 2 thr/row ---------
__global__ __launch_bounds__(256)
void attn_kernel(const int* __restrict__ edge_index) {
    extern __shared__ float smf[];
    float* Kt = smf;
    float* Vt = smf + NG * DK;
    float* S  = smf + 2 * NG * DK;   // [128][129]

    const int g = blockIdx.x >> 3;
    const int h = blockIdx.x & 7;
    const int tid = threadIdx.x;
    const int i = tid >> 1, hf = tid & 1;

    const float* Kg = g_QKV + NSZ     + (size_t)g * NG * D_MODEL + h * DK;
    const float* Vg = g_QKV + 2 * NSZ + (size_t)g * NG * D_MODEL + h * DK;

    for (int idx = tid; idx < NG * DK / 4; idx += 256) {
        int row = idx >> 4;
        int c4  = idx & 15;
        ((float4*)Kt)[row * 16 + c4] = *(const float4*)(Kg + (size_t)row * D_MODEL + c4 * 4);
        ((float4*)Vt)[row * 16 + c4] = *(const float4*)(Vg + (size_t)row * D_MODEL + c4 * 4);
    }

    float qv[DK];
    const float* Qg = g_QKV + (size_t)(g * NG + i) * D_MODEL + h * DK;
    #pragma unroll
    for (int d = 0; d < DK; d += 4) {
        float4 v = *(const float4*)(Qg + d);
        qv[d] = v.x; qv[d + 1] = v.y; qv[d + 2] = v.z; qv[d + 3] = v.w;
    }
    __syncthreads();

    // scores: this thread owns j in [hf*64, hf*64+64)
    const float scale = 0.125f;
    const int jb = hf * 64;
    for (int j = jb; j < jb + 64; j++) {
        float s0 = 0.f, s1 = 0.f, s2 = 0.f, s3 = 0.f;
        #pragma unroll
        for (int d = 0; d < DK; d += 4) {
            float4 kv = *(const float4*)(Kt + j * DK + d);
            s0 = fmaf(qv[d],     kv.x, s0);
            s1 = fmaf(qv[d + 1], kv.y, s1);
            s2 = fmaf(qv[d + 2], kv.z, s2);
            s3 = fmaf(qv[d + 3], kv.w, s3);
        }
        S[i * 129 + j] = ((s0 + s1) + (s2 + s3)) * scale;
    }
    __syncthreads();

    // scatter precomputed edge bias (edges for graph g are contiguous)
    const int* srcp = edge_index;
    const int* dstp = edge_index + NEDGES;
    for (int t = tid; t < EPG; t += 256) {
        int e  = g * EPG + t;
        int ls = srcp[e] & (NG - 1);
        int ld = dstp[e] & (NG - 1);
        atomicAdd(&S[ls * 129 + ld], g_EB[(size_t)e * 8 + h]);
    }
    __syncthreads();

    // softmax over row i, split across the thread pair, merged via shfl
    float m = -1e30f;
    for (int j = jb; j < jb + 64; j++) m = fmaxf(m, S[i * 129 + j]);
    m = fmaxf(m, __shfl_xor_sync(0xFFFFFFFFu, m, 1));
    float sum = 0.f;
    for (int j = jb; j < jb + 64; j++) {
        float p = __expf(S[i * 129 + j] - m);
        S[i * 129 + j] = p;
        sum += p;
    }
    sum += __shfl_xor_sync(0xFFFFFFFFu, sum, 1);
    float inv = 1.f / sum;
    __syncwarp();   // pair writes S within same warp; make them visible

    // PV: this thread owns d in [hf*32, hf*32+32), sums over all 128 j
    const int db = hf * 32;
    float acc[32];
    #pragma unroll
    for (int d = 0; d < 32; d++) acc[d] = 0.f;
    for (int j = 0; j < NG; j++) {
        float p = S[i * 129 + j];
        #pragma unroll
        for (int d = 0; d < 32; d += 4) {
            float4 v = *(const float4*)(Vt + j * DK + db + d);
            acc[d]     = fmaf(p, v.x, acc[d]);
            acc[d + 1] = fmaf(p, v.y, acc[d + 1]);
            acc[d + 2] = fmaf(p, v.z, acc[d + 2]);
            acc[d + 3] = fmaf(p, v.w, acc[d + 3]);
        }
    }

    // write fp16 hi/lo directly (feeds O-projection GEMM)
    const size_t ob = (size_t)(g * NG + i) * D_MODEL + h * DK + db;
    #pragma unroll
    for (int d = 0; d < 32; d += 4) {
        __half hv[4], lv[4];
        #pragma unroll
        for (int u = 0; u < 4; u++) split_h(acc[d + u] * inv, hv[u], lv[u]);
        *(uint2*)(g_Ohi + ob + d) = *(uint2*)hv;
        *(uint2*)(g_Olo + ob + d) = *(uint2*)lv;
    }
}

// ---------------- launcher ---------------------------------------------------
extern "C" void kernel_launch(void* const* d_in, const int* in_sizes, int n_in,
                              void* d_out, int out_size) {
    const float* x    = (const float*)d_in[0];
    const int*   eidx = (const int*)  d_in[1];
    const float* ea   = (const float*)d_in[2];
    const float* Wq = (const float*)d_in[5];
    const float* bq = (const float*)d_in[6];
    const float* Wk = (const float*)d_in[7];
    const float* bk = (const float*)d_in[8];
    const float* Wv = (const float*)d_in[9];
    const float* bv = (const float*)d_in[10];
    const float* Wo = (const float*)d_in[11];
    const float* bo = (const float*)d_in[12];
    const float* W1 = (const float*)d_in[13];
    const float* b1 = (const float*)d_in[14];
    const float* W2 = (const float*)d_in[15];
    const float* b2 = (const float*)d_in[16];
    float* out = (float*)d_out;

    float *QKVp, *EBp;
    __half *Xh, *Xl, *Oh, *Ol, *WTh, *WTl;
    cudaGetSymbolAddress((void**)&QKVp, g_QKV);
    cudaGetSymbolAddress((void**)&EBp,  g_EB);
    cudaGetSymbolAddress((void**)&Xh,   g_Xhi);
    cudaGetSymbolAddress((void**)&Xl,   g_Xlo);
    cudaGetSymbolAddress((void**)&Oh,   g_Ohi);
    cudaGetSymbolAddress((void**)&Ol,   g_Olo);
    cudaGetSymbolAddress((void**)&WTh,  g_WThi);
    cudaGetSymbolAddress((void**)&WTl,  g_WTlo);

    cudaFuncSetAttribute(gemm_mma<1>, cudaFuncAttributeMaxDynamicSharedMemorySize, 2 * 20480);
    cudaFuncSetAttribute(gemm_mma<3>, cudaFuncAttributeMaxDynamicSharedMemorySize, 2 * 40960);
    const int attn_smem = (2 * NG * DK + NG * 129) * (int)sizeof(float);
    cudaFuncSetAttribute(attn_kernel, cudaFuncAttributeMaxDynamicSharedMemorySize, attn_smem);

    prep_w4<<<dim3(16, 16, 4), 256>>>(Wq, Wk, Wv, Wo, WTh, WTl);
    prep_split<<<NSZ / 1024, 256>>>(x, Xh, Xl);

    // Q, K: single-pass fp16 (score path is softmax-damped)
    gemm_mma<1><<<dim3(4, 64, 2), 256, 2 * 20480>>>(Xh, Xl, WTh, WTl, bq, bk, bk, QKVp);
    // V: 3-term fp16 split (straight-through precision path)
    gemm_mma<3><<<dim3(4, 64, 1), 256, 2 * 40960>>>(Xh, Xl, WTh + 2 * WSZ, WTl + 2 * WSZ,
                                                    bv, bv, bv, QKVp + 2 * (size_t)NSZ);

    edge_mlp_mma<<<NEDGES / 512, 256>>>(ea, W1, b1, W2, b2, EBp);

    attn_kernel<<<NGRAPHS * NHEADS, 256, attn_smem>>>(eidx);

    // O projection: 3-term fp16 split
    gemm_mma<3><<<dim3(4, 64, 1), 256, 2 * 40960>>>(Oh, Ol, WTh + 3 * WSZ, WTl + 3 * WSZ,
                                                    bo, bo, bo, out);
}

// round 14
// speedup vs baseline: 3.0105x; 1.4915x over previous
#include <cuda_runtime.h>
#include <cuda_bf16.h>
#include <cuda_fp16.h>
#include <cstdint>

#define D_MODEL 512
#define NHEADS  8
#define DK      64
#define NG      128
#define NGRAPHS 64
#define NNODES  8192
#define EPG     4096
#define NEDGES  262144
#define KPAD    40
#define W2PAD   520
#define NSZ     (NNODES * D_MODEL)
#define WSZ     (D_MODEL * D_MODEL)

// ---------------- scratch (static device allocations) ----------------------
__device__ float g_EB [NEDGES * NHEADS];

__device__ __half g_QKh[2 * NSZ];    // fp16 Q,K (GEMM output)
__device__ __half g_Vh [NSZ];        // fp16 V hi/lo (GEMM output, 3-term)
__device__ __half g_Vl [NSZ];
__device__ __half g_Xhi[NSZ];
__device__ __half g_Xlo[NSZ];
__device__ __half g_Ohi[NSZ];
__device__ __half g_Olo[NSZ];
__device__ __half g_WThi[4 * WSZ];   // [n][k] transposed
__device__ __half g_WTlo[4 * WSZ];

// ---------------- helpers ---------------------------------------------------
__device__ __forceinline__ uint32_t smem_u32(const void* p) {
    uint32_t a;
    asm("{ .reg .u64 t; cvta.to.shared.u64 t, %1; cvt.u32.u64 %0, t; }" : "=r"(a) : "l"(p));
    return a;
}
__device__ __forceinline__ void split_h(float v, __half& hi, __half& lo) {
    hi = __float2half_rn(v);
    lo = __float2half_rn(v - __half2float(hi));
}
__device__ __forceinline__ uint32_t pack_bf16x2(float lo_elem, float hi_elem) {
    uint32_t r;
    asm("cvt.rn.bf16x2.f32 %0, %1, %2;" : "=r"(r) : "f"(hi_elem), "f"(lo_elem));
    return r;
}
__device__ __forceinline__ void mma16816h(float* d, const uint32_t* a, uint32_t b0, uint32_t b1) {
    asm volatile(
        "mma.sync.aligned.m16n8k16.row.col.f32.f16.f16.f32 "
        "{%0,%1,%2,%3}, {%4,%5,%6,%7}, {%8,%9}, {%0,%1,%2,%3};"
        : "+f"(d[0]), "+f"(d[1]), "+f"(d[2]), "+f"(d[3])
        : "r"(a[0]), "r"(a[1]), "r"(a[2]), "r"(a[3]), "r"(b0), "r"(b1));
}
__device__ __forceinline__ void mma16816(float* d, const uint32_t* a, uint32_t b0, uint32_t b1) {
    asm volatile(
        "mma.sync.aligned.m16n8k16.row.col.f32.bf16.bf16.f32 "
        "{%0,%1,%2,%3}, {%4,%5,%6,%7}, {%8,%9}, {%0,%1,%2,%3};"
        : "+f"(d[0]), "+f"(d[1]), "+f"(d[2]), "+f"(d[3])
        : "r"(a[0]), "r"(a[1]), "r"(a[2]), "r"(a[3]), "r"(b0), "r"(b1));
}

#define CP16(dst, src) asm volatile("cp.async.cg.shared.global [%0], [%1], 16;" :: "r"(dst), "l"(src))
#define CPCOMMIT()     asm volatile("cp.async.commit_group;")
#define CPWAIT1()      asm volatile("cp.async.wait_group 1;")
#define CPWAIT0()      asm volatile("cp.async.wait_group 0;")
#define LDSM4(R0,R1,R2,R3,A) \
    asm volatile("ldmatrix.sync.aligned.m8n8.x4.shared.b16 {%0,%1,%2,%3}, [%4];" \
                 : "=r"(R0), "=r"(R1), "=r"(R2), "=r"(R3) : "r"(A))

// ---------------- prep: elementwise hi/lo split (fp16) -----------------------
__global__ __launch_bounds__(256)
void prep_split(const float* __restrict__ X, __half* __restrict__ hi,
                __half* __restrict__ lo) {
    int i = (blockIdx.x * 256 + threadIdx.x) * 4;
    float4 v = *(const float4*)(X + i);
    __half h[4], l[4];
    split_h(v.x, h[0], l[0]);
    split_h(v.y, h[1], l[1]);
    split_h(v.z, h[2], l[2]);
    split_h(v.w, h[3], l[3]);
    *(uint2*)(hi + i) = *(uint2*)h;
    *(uint2*)(lo + i) = *(uint2*)l;
}

// ---------------- prep: 4 weights transpose + split ---------------------------
__global__ __launch_bounds__(256)
void prep_w4(const float* __restrict__ W0, const float* __restrict__ W1p,
             const float* __restrict__ W2p, const float* __restrict__ W3,
             __half* __restrict__ Thi, __half* __restrict__ Tlo) {
    __shared__ float tile[32][33];
    const int z = blockIdx.z;
    const float* W = (z == 0) ? W0 : (z == 1) ? W1p : (z == 2) ? W2p : W3;
    __half* Th = Thi + (size_t)z * WSZ;
    __half* Tl = Tlo + (size_t)z * WSZ;
    const int k0 = blockIdx.y * 32, n0 = blockIdx.x * 32;
    const int tx = threadIdx.x & 31, ty = threadIdx.x >> 5;
    #pragma unroll
    for (int r = ty; r < 32; r += 8)
        tile[r][tx] = W[(size_t)(k0 + r) * D_MODEL + n0 + tx];
    __syncthreads();
    #pragma unroll
    for (int r = ty; r < 32; r += 8) {
        float v = tile[tx][r];
        __half h, l;
        split_h(v, h, l);
        size_t o = (size_t)(n0 + r) * D_MODEL + k0 + tx;
        Th[o] = h;
        Tl[o] = l;
    }
}

// ---------------- fp16 mma GEMM ------------------------------------------------
// NT=1 single-pass (3-stage pipe, 1 sync/iter), NT=3 error split (2-stage).
// OUTM: 0 = f32 out, 1 = f16 out, 2 = f16 hi/lo out.
template <int NT, int OUTM>
__global__ __launch_bounds__(256, 2)
void gemm_mma(const __half* __restrict__ Ahi, const __half* __restrict__ Alo,
              const __half* __restrict__ WTh, const __half* __restrict__ WTl,
              const float* __restrict__ bz0, const float* __restrict__ bz1,
              const float* __restrict__ bz2, void* __restrict__ Cb,
              __half* __restrict__ Clo) {
    extern __shared__ char smc[];
    const uint32_t smb = smem_u32(smc);
    constexpr uint32_t STG = (NT == 3) ? 40960u : 20480u;
    constexpr uint32_t OBH = (NT == 3) ? 20480u : 10240u;

    const int z = blockIdx.z;
    const __half* Bhi = WTh + (size_t)z * WSZ;
    const __half* Blo = WTl + (size_t)z * WSZ;
    const float* bias = (z == 0) ? bz0 : (z == 1) ? bz1 : bz2;

    const int tid = threadIdx.x, lane = tid & 31, wid = tid >> 5;
    const int wm = (wid & 3) * 32, wn = (wid >> 2) * 64;
    const int bn = blockIdx.x * 128, bm = blockIdx.y * 128;
    const int grp = lane >> 2, th = lane & 3;

    const int lr  = tid >> 2;
    const int lcb = (tid & 3) * 16;

    const int l07 = lane & 7, q = lane >> 3;
    const uint32_t aOff = (uint32_t)(((wm + l07 + (q & 1) * 8) * KPAD + (q >> 1) * 8) * 2);
    const uint32_t bOff = (uint32_t)(((wn + l07 + (q >> 1) * 8) * KPAD + (q & 1) * 8) * 2);

    float acc[2][8][4];
    #pragma unroll
    for (int mi = 0; mi < 2; mi++)
        #pragma unroll
        for (int ni = 0; ni < 8; ni++)
            #pragma unroll
            for (int j = 0; j < 4; j++) acc[mi][ni][j] = 0.f;

    auto load_stage = [&](int s, int k0) {
        uint32_t sb = smb + (uint32_t)s * STG;
        #pragma unroll
        for (int p = 0; p < 2; p++) {
            int r = p * 64 + lr;
            uint32_t d = sb + (uint32_t)(r * 80 + lcb);
            CP16(d,       (const char*)(Ahi + (size_t)(bm + r) * D_MODEL + k0) + lcb);
            CP16(d + OBH, (const char*)(Bhi + (size_t)(bn + r) * D_MODEL + k0) + lcb);
            if (NT == 3) {
                CP16(d + 10240, (const char*)(Alo + (size_t)(bm + r) * D_MODEL + k0) + lcb);
                CP16(d + 30720, (const char*)(Blo + (size_t)(bn + r) * D_MODEL + k0) + lcb);
            }
        }
    };

    auto do_compute = [&](uint32_t stb) {
        #pragma unroll
        for (int ks = 0; ks < 32; ks += 16) {
            uint32_t ah[2][4], al[2][4];
            uint32_t aAdr = stb + aOff + ks * 2;
            LDSM4(ah[0][0], ah[0][1], ah[0][2], ah[0][3], aAdr);
            LDSM4(ah[1][0], ah[1][1], ah[1][2], ah[1][3], aAdr + 1280);
            if (NT == 3) {
                LDSM4(al[0][0], al[0][1], al[0][2], al[0][3], aAdr + 10240);
                LDSM4(al[1][0], al[1][1], al[1][2], al[1][3], aAdr + 11520);
            }
            #pragma unroll
            for (int half = 0; half < 2; half++) {
                uint32_t bh[2][4], bu[2][4];
                #pragma unroll
                for (int p = 0; p < 2; p++) {
                    uint32_t bAdr = stb + OBH + bOff + ks * 2 + (half * 2 + p) * 1280;
                    LDSM4(bh[p][0], bh[p][1], bh[p][2], bh[p][3], bAdr);
                    if (NT == 3) LDSM4(bu[p][0], bu[p][1], bu[p][2], bu[p][3], bAdr + 10240);
                }
                #pragma unroll
                for (int p = 0; p < 2; p++)
                    #pragma unroll
                    for (int mi = 0; mi < 2; mi++) {
                        const int ni = half * 4 + p * 2;
                        mma16816h(acc[mi][ni],     ah[mi], bh[p][0], bh[p][1]);
                        mma16816h(acc[mi][ni + 1], ah[mi], bh[p][2], bh[p][3]);
                    }
                if (NT == 3) {
                    #pragma unroll
                    for (int p = 0; p < 2; p++)
                        #pragma unroll
                        for (int mi = 0; mi < 2; mi++) {
                            const int ni = half * 4 + p * 2;
                            mma16816h(acc[mi][ni],     ah[mi], bu[p][0], bu[p][1]);
                            mma16816h(acc[mi][ni + 1], ah[mi], bu[p][2], bu[p][3]);
                        }
                    #pragma unroll
                    for (int p = 0; p < 2; p++)
                        #pragma unroll
                        for (int mi = 0; mi < 2; mi++) {
                            const int ni = half * 4 + p * 2;
                            mma16816h(acc[mi][ni],     al[mi], bh[p][0], bh[p][1]);
                            mma16816h(acc[mi][ni + 1], al[mi], bh[p][2], bh[p][3]);
                        }
                }
            }
        }
    };

    if constexpr (NT == 1) {
        // 3-stage, single sync per iteration
        load_stage(0, 0);  CPCOMMIT();
        load_stage(1, 32); CPCOMMIT();
        #pragma unroll 1
        for (int it = 0; it < 16; it++) {
            if (it < 14) CPWAIT1(); else CPWAIT0();
            __syncthreads();
            if (it + 2 < 16) { load_stage((it + 2) % 3, (it + 2) * 32); CPCOMMIT(); }
            do_compute(smb + (uint32_t)(it % 3) * STG);
        }
    } else {
        load_stage(0, 0); CPCOMMIT();
        #pragma unroll 1
        for (int it = 0; it < 16; it++) {
            if (it < 15) {
                load_stage((it + 1) & 1, (it + 1) * 32);
                CPCOMMIT();
                CPWAIT1();
            } else {
                CPWAIT0();
            }
            __syncthreads();
            do_compute(smb + (uint32_t)(it & 1) * STG);
            __syncthreads();
        }
    }

    #pragma unroll
    for (int mi = 0; mi < 2; mi++) {
        int row = bm + wm + mi * 16 + grp;
        #pragma unroll
        for (int ni = 0; ni < 8; ni++) {
            int col = bn + wn + ni * 8 + th * 2;
            float bx = bias[col], by = bias[col + 1];
            float v0 = acc[mi][ni][0] + bx, v1 = acc[mi][ni][1] + by;
            float v2 = acc[mi][ni][2] + bx, v3 = acc[mi][ni][3] + by;
            if constexpr (OUTM == 0) {
                float* C = (float*)Cb + (size_t)z * NSZ;
                *(float2*)&C[(size_t)row * D_MODEL + col]       = make_float2(v0, v1);
                *(float2*)&C[(size_t)(row + 8) * D_MODEL + col] = make_float2(v2, v3);
            } else if constexpr (OUTM == 1) {
                __half* C = (__half*)Cb + (size_t)z * NSZ;
                *(__half2*)&C[(size_t)row * D_MODEL + col]       = __floats2half2_rn(v0, v1);
                *(__half2*)&C[(size_t)(row + 8) * D_MODEL + col] = __floats2half2_rn(v2, v3);
            } else {
                __half* Ch = (__half*)Cb;
                __half h0, h1, h2, h3, l0, l1, l2, l3;
                split_h(v0, h0, l0); split_h(v1, h1, l1);
                split_h(v2, h2, l2); split_h(v3, h3, l3);
                __half hp0[2] = {h0, h1}, hp1[2] = {h2, h3};
                __half lp0[2] = {l0, l1}, lp1[2] = {l2, l3};
                *(uint32_t*)&Ch [(size_t)row * D_MODEL + col]       = *(uint32_t*)hp0;
                *(uint32_t*)&Ch [(size_t)(row + 8) * D_MODEL + col] = *(uint32_t*)hp1;
                *(uint32_t*)&Clo[(size_t)row * D_MODEL + col]       = *(uint32_t*)lp0;
                *(uint32_t*)&Clo[(size_t)(row + 8) * D_MODEL + col] = *(uint32_t*)lp1;
            }
        }
    }
}

// ---------------- edge MLP on tensor cores: 64 edges/warp --------------------
__global__ __launch_bounds__(256)
void edge_mlp_mma(const float* __restrict__ ea,
                  const float* __restrict__ W1, const float* __restrict__ b1,
                  const float* __restrict__ W2, const float* __restrict__ b2,
                  float* __restrict__ eb) {
    __shared__ __nv_bfloat16 w1e[D_MODEL * 8];
    __shared__ __nv_bfloat16 w2t[8 * W2PAD];

    const int tid = threadIdx.x;
    for (int j = tid; j < D_MODEL; j += 256) {
        #pragma unroll
        for (int c = 0; c < 4; c++) w1e[j * 8 + c] = __float2bfloat16(W1[c * D_MODEL + j]);
        w1e[j * 8 + 4] = __float2bfloat16(b1[j]);
        w1e[j * 8 + 5] = __float2bfloat16(0.f);
        w1e[j * 8 + 6] = __float2bfloat16(0.f);
        w1e[j * 8 + 7] = __float2bfloat16(0.f);
        #pragma unroll
        for (int h = 0; h < 8; h++) w2t[h * W2PAD + j] = __float2bfloat16(W2[j * 8 + h]);
    }
    __syncthreads();

    const int lane = tid & 31, wid = tid >> 5;
    const int grp = lane >> 2, th = lane & 3;
    const int e0 = blockIdx.x * 512 + wid * 64;
    const uint32_t zero = 0;

    uint32_t ea0[4], ea1[4];
    if (th < 2) {
        #pragma unroll
        for (int t = 0; t < 4; t++) {
            float2 v0 = *(const float2*)(ea + (size_t)(e0 + t * 16 + grp) * 4 + th * 2);
            float2 v1 = *(const float2*)(ea + (size_t)(e0 + t * 16 + grp + 8) * 4 + th * 2);
            ea0[t] = pack_bf16x2(v0.x, v0.y);
            ea1[t] = pack_bf16x2(v1.x, v1.y);
        }
    } else if (th == 2) {
        uint32_t one = pack_bf16x2(1.f, 0.f);
        #pragma unroll
        for (int t = 0; t < 4; t++) { ea0[t] = one; ea1[t] = one; }
    } else {
        #pragma unroll
        for (int t = 0; t < 4; t++) { ea0[t] = 0u; ea1[t] = 0u; }
    }

    float acc[4][4];
    {
        float bz0 = b2[2 * th], bz1 = b2[2 * th + 1];
        #pragma unroll
        for (int t = 0; t < 4; t++) {
            acc[t][0] = bz0; acc[t][1] = bz1; acc[t][2] = bz0; acc[t][3] = bz1;
        }
    }

    #pragma unroll 2
    for (int jj = 0; jj < D_MODEL; jj += 16) {
        uint32_t ha[4][4];
        #pragma unroll
        for (int half = 0; half < 2; half++) {
            const int j0 = jj + half * 8;
            uint32_t w1f = *(const uint32_t*)&w1e[(j0 + grp) * 8 + th * 2];
            #pragma unroll
            for (int t = 0; t < 4; t++) {
                float c[4] = {0.f, 0.f, 0.f, 0.f};
                uint32_t av[4] = {ea0[t], ea1[t], zero, zero};
                mma16816(c, av, w1f, zero);
                ha[t][half * 2 + 0] = pack_bf16x2(fmaxf(c[0], 0.f), fmaxf(c[1], 0.f));
                ha[t][half * 2 + 1] = pack_bf16x2(fmaxf(c[2], 0.f), fmaxf(c[3], 0.f));
            }
        }
        uint32_t w2f0 = *(const uint32_t*)&w2t[grp * W2PAD + jj + th * 2];
        uint32_t w2f1 = *(const uint32_t*)&w2t[grp * W2PAD + jj + 8 + th * 2];
        #pragma unroll
        for (int t = 0; t < 4; t++) mma16816(acc[t], ha[t], w2f0, w2f1);
    }

    #pragma unroll
    for (int t = 0; t < 4; t++) {
        *(float2*)(eb + (size_t)(e0 + t * 16 + grp) * 8 + 2 * th) =
            make_float2(acc[t][0], acc[t][1]);
        *(float2*)(eb + (size_t)(e0 + t * 16 + grp + 8) * 8 + 2 * th) =
            make_float2(acc[t][2], acc[t][3]);
    }
}

// ---------------- tensorized block-diagonal attention ------------------------
// smem bytes: S[128][130] f32 @0 (66560) | Q @66560 [128][72] h | K @84992 [128][72]
// Ph aliases @66560 [128][136] | Pl @103424 | Vh @138240 [64][136] | Vl @155648
// invS @173056 (512). total 173568.
__global__ __launch_bounds__(256)
void attn_mma(const int* __restrict__ edge_index) {
    extern __shared__ char smc[];
    const uint32_t smb = smem_u32(smc);
    float*  S    = (float*)smc;
    __half* Qs   = (__half*)(smc + 66560);
    __half* Ks   = (__half*)(smc + 84992);
    __half* Phm  = (__half*)(smc + 66560);
    __half* Plm  = (__half*)(smc + 103424);
    __half* Vhs  = (__half*)(smc + 138240);
    __half* Vls  = (__half*)(smc + 155648);
    float*  invS = (float*)(smc + 173056);

    const int g = blockIdx.x >> 3, h = blockIdx.x & 7;
    const int tid = threadIdx.x, lane = tid & 31, wid = tid >> 5;
    const int grp = lane >> 2, th = lane & 3;
    const int l07 = lane & 7, q = lane >> 3;

    // ---- loads: Q,K fp16 rows; V hi/lo transposed to [d][j]
    const __half* Qg = g_QKh +           (size_t)(g * NG) * D_MODEL + h * DK;
    const __half* Kg = g_QKh + NSZ +     (size_t)(g * NG) * D_MODEL + h * DK;
    const __half* Vgh = g_Vh + (size_t)(g * NG) * D_MODEL + h * DK;
    const __half* Vgl = g_Vl + (size_t)(g * NG) * D_MODEL + h * DK;
    #pragma unroll
    for (int idx = tid; idx < 1024; idx += 256) {
        int r = idx >> 3, c8 = (idx & 7) * 8;
        *(uint4*)&Qs[r * 72 + c8] = *(const uint4*)&Qg[(size_t)r * D_MODEL + c8];
        *(uint4*)&Ks[r * 72 + c8] = *(const uint4*)&Kg[(size_t)r * D_MODEL + c8];
        uint4 hv = *(const uint4*)&Vgh[(size_t)r * D_MODEL + c8];
        uint4 lv = *(const uint4*)&Vgl[(size_t)r * D_MODEL + c8];
        const __half* hp = (const __half*)&hv;
        const __half* lp = (const __half*)&lv;
        #pragma unroll
        for (int u = 0; u < 8; u++) {
            Vhs[(c8 + u) * 136 + r] = hp[u];
            Vls[(c8 + u) * 136 + r] = lp[u];
        }
    }
    __syncthreads();

    // ---- S = Q K^T * scale : M=128 N=128 K=64, warp tile 32x64
    {
        const int wm = (wid & 3) * 32, wn = (wid >> 2) * 64;
        uint32_t qOff = smb + 66560u + (uint32_t)(((wm + l07 + (q & 1) * 8) * 72 + (q >> 1) * 8) * 2);
        uint32_t kOff = smb + 84992u + (uint32_t)(((wn + l07 + (q >> 1) * 8) * 72 + (q & 1) * 8) * 2);

        float acc[2][8][4] = {};
        #pragma unroll
        for (int kk = 0; kk < 4; kk++) {
            uint32_t a0[4], a1[4];
            LDSM4(a0[0], a0[1], a0[2], a0[3], qOff + kk * 32);
            LDSM4(a1[0], a1[1], a1[2], a1[3], qOff + kk * 32 + 16 * 72 * 2);
            #pragma unroll
            for (int nip = 0; nip < 4; nip++) {
                uint32_t b0, b1, b2, b3;
                LDSM4(b0, b1, b2, b3, kOff + kk * 32 + nip * 16 * 72 * 2);
                mma16816h(acc[0][nip * 2],     a0, b0, b1);
                mma16816h(acc[0][nip * 2 + 1], a0, b2, b3);
                mma16816h(acc[1][nip * 2],     a1, b0, b1);
                mma16816h(acc[1][nip * 2 + 1], a1, b2, b3);
            }
        }
        #pragma unroll
        for (int mi = 0; mi < 2; mi++) {
            int r = wm + mi * 16 + grp;
            #pragma unroll
            for (int ni = 0; ni < 8; ni++) {
                int c = wn + ni * 8 + th * 2;
                *(float2*)&S[r * 130 + c] =
                    make_float2(acc[mi][ni][0] * 0.125f, acc[mi][ni][1] * 0.125f);
                *(float2*)&S[(r + 8) * 130 + c] =
                    make_float2(acc[mi][ni][2] * 0.125f, acc[mi][ni][3] * 0.125f);
            }
        }
    }
    __syncthreads();

    // ---- edge bias scatter
    const int* srcp = edge_index;
    const int* dstp = edge_index + NEDGES;
    for (int t = tid; t < EPG; t += 256) {
        int e = g * EPG + t;
        atomicAdd(&S[(srcp[e] & (NG - 1)) * 130 + (dstp[e] & (NG - 1))],
                  g_EB[(size_t)e * 8 + h]);
    }
    __syncthreads();

    // ---- softmax (2 threads/row) -> unnormalized P hi/lo, invS
    {
        const int i = tid >> 1, hf = tid & 1, jb = hf * 64;
        float m = -1e30f;
        for (int j = jb; j < jb + 64; j++) m = fmaxf(m, S[i * 130 + j]);
        m = fmaxf(m, __shfl_xor_sync(0xFFFFFFFFu, m, 1));
        float sum = 0.f;
        for (int j = jb; j < jb + 64; j += 2) {
            float p0 = __expf(S[i * 130 + j] - m);
            float p1 = __expf(S[i * 130 + j + 1] - m);
            sum += p0 + p1;
            __half h0, h1, l0, l1;
            split_h(p0, h0, l0);
            split_h(p1, h1, l1);
            __half hp[2] = {h0, h1}, lp[2] = {l0, l1};
            *(uint32_t*)&Phm[i * 136 + j] = *(uint32_t*)hp;
            *(uint32_t*)&Plm[i * 136 + j] = *(uint32_t*)lp;
        }
        sum += __shfl_xor_sync(0xFFFFFFFFu, sum, 1);
        if (hf == 0) invS[i] = 1.f / sum;
    }
    __syncthreads();

    // ---- out = (P V) * inv : M=128 N=64 K=128, warp tile 32x32, 3 terms
    {
        const int wm2 = (wid & 3) * 32, wn2 = (wid >> 2) * 32;
        uint32_t pOh = smb + 66560u  + (uint32_t)(((wm2 + l07 + (q & 1) * 8) * 136 + (q >> 1) * 8) * 2);
        uint32_t pOl = smb + 103424u + (uint32_t)(((wm2 + l07 + (q & 1) * 8) * 136 + (q >> 1) * 8) * 2);
        uint32_t vOh = smb + 138240u + (uint32_t)(((wn2 + l07 + (q >> 1) * 8) * 136 + (q & 1) * 8) * 2);
        uint32_t vOl = smb + 155648u + (uint32_t)(((wn2 + l07 + (q >> 1) * 8) * 136 + (q & 1) * 8) * 2);

        float o[2][4][4] = {};
        #pragma unroll
        for (int kk = 0; kk < 8; kk++) {
            uint32_t ph[2][4], pl[2][4], vh[2][4], vl[2][4];
            LDSM4(ph[0][0], ph[0][1], ph[0][2], ph[0][3], pOh + kk * 32);
            LDSM4(ph[1][0], ph[1][1], ph[1][2], ph[1][3], pOh + kk * 32 + 16 * 136 * 2);
            LDSM4(pl[0][0], pl[0][1], pl[0][2], pl[0][3], pOl + kk * 32);
            LDSM4(pl[1][0], pl[1][1], pl[1][2], pl[1][3], pOl + kk * 32 + 16 * 136 * 2);
            LDSM4(vh[0][0], vh[0][1], vh[0][2], vh[0][3], vOh + kk * 32);
            LDSM4(vh[1][0], vh[1][1], vh[1][2], vh[1][3], vOh + kk * 32 + 16 * 136 * 2);
            LDSM4(vl[0][0], vl[0][1], vl[0][2], vl[0][3], vOl + kk * 32);
            LDSM4(vl[1][0], vl[1][1], vl[1][2], vl[1][3], vOl + kk * 32 + 16 * 136 * 2);
            #pragma unroll
            for (int nip = 0; nip < 2; nip++)
                #pragma unroll
                for (int mi = 0; mi < 2; mi++) {
                    mma16816h(o[mi][nip * 2],     ph[mi], vh[nip][0], vh[nip][1]);
                    mma16816h(o[mi][nip * 2 + 1], ph[mi], vh[nip][2], vh[nip][3]);
                }
            #pragma unroll
            for (int nip = 0; nip < 2; nip++)
                #pragma unroll
                for (int mi = 0; mi < 2; mi++) {
                    mma16816h(o[mi][nip * 2],     ph[mi], vl[nip][0], vl[nip][1]);
                    mma16816h(o[mi][nip * 2 + 1], ph[mi], vl[nip][2], vl[nip][3]);
                }
            #pragma unroll
            for (int nip = 0; nip < 2; nip++)
                #pragma unroll
                for (int mi = 0; mi < 2; mi++) {
                    mma16816h(o[mi][nip * 2],     pl[mi], vh[nip][0], vh[nip][1]);
                    mma16816h(o[mi][nip * 2 + 1], pl[mi], vh[nip][2], vh[nip][3]);
                }
        }

        #pragma unroll
        for (int mi = 0; mi < 2; mi++) {
            int r = wm2 + mi * 16 + grp;
            float iv0 = invS[r], iv1 = invS[r + 8];
            size_t b0 = (size_t)(g * NG + r) * D_MODEL + h * DK;
            size_t b1 = (size_t)(g * NG + r + 8) * D_MODEL + h * DK;
            #pragma unroll
            for (int ni = 0; ni < 4; ni++) {
                int c = wn2 + ni * 8 + th * 2;
                float f0 = o[mi][ni][0] * iv0, f1 = o[mi][ni][1] * iv0;
                float f2 = o[mi][ni][2] * iv1, f3 = o[mi][ni][3] * iv1;
                __half h0, h1, h2, h3, l0, l1, l2, l3;
                split_h(f0, h0, l0); split_h(f1, h1, l1);
                split_h(f2, h2, l2); split_h(f3, h3, l3);
                __half hp0[2] = {h0, h1}, hp1[2] = {h2, h3};
                __half lp0[2] = {l0, l1}, lp1[2] = {l2, l3};
                *(uint32_t*)&g_Ohi[b0 + c] = *(uint32_t*)hp0;
                *(uint32_t*)&g_Ohi[b1 + c] = *(uint32_t*)hp1;
                *(uint32_t*)&g_Olo[b0 + c] = *(uint32_t*)lp0;
                *(uint32_t*)&g_Olo[b1 + c] = *(uint32_t*)lp1;
            }
        }
    }
}

// ---------------- launcher ---------------------------------------------------
extern "C" void kernel_launch(void* const* d_in, const int* in_sizes, int n_in,
                              void* d_out, int out_size) {
    const float* x    = (const float*)d_in[0];
    const int*   eidx = (const int*)  d_in[1];
    const float* ea   = (const float*)d_in[2];
    const float* Wq = (const float*)d_in[5];
    const float* bq = (const float*)d_in[6];
    const float* Wk = (const float*)d_in[7];
    const float* bk = (const float*)d_in[8];
    const float* Wv = (const float*)d_in[9];
    const float* bv = (const float*)d_in[10];
    const float* Wo = (const float*)d_in[11];
    const float* bo = (const float*)d_in[12];
    const float* W1 = (const float*)d_in[13];
    const float* b1 = (const float*)d_in[14];
    const float* W2 = (const float*)d_in[15];
    const float* b2 = (const float*)d_in[16];
    float* out = (float*)d_out;

    float* EBp;
    __half *Xh, *Xl, *Oh, *Ol, *WTh, *WTl, *QKh, *Vhp, *Vlp;
    cudaGetSymbolAddress((void**)&EBp, g_EB);
    cudaGetSymbolAddress((void**)&Xh,  g_Xhi);
    cudaGetSymbolAddress((void**)&Xl,  g_Xlo);
    cudaGetSymbolAddress((void**)&Oh,  g_Ohi);
    cudaGetSymbolAddress((void**)&Ol,  g_Olo);
    cudaGetSymbolAddress((void**)&WTh, g_WThi);
    cudaGetSymbolAddress((void**)&WTl, g_WTlo);
    cudaGetSymbolAddress((void**)&QKh, g_QKh);
    cudaGetSymbolAddress((void**)&Vhp, g_Vh);
    cudaGetSymbolAddress((void**)&Vlp, g_Vl);

    cudaFuncSetAttribute(gemm_mma<1, 1>, cudaFuncAttributeMaxDynamicSharedMemorySize, 3 * 20480);
    cudaFuncSetAttribute(gemm_mma<3, 2>, cudaFuncAttributeMaxDynamicSharedMemorySize, 2 * 40960);
    cudaFuncSetAttribute(gemm_mma<3, 0>, cudaFuncAttributeMaxDynamicSharedMemorySize, 2 * 40960);
    cudaFuncSetAttribute(attn_mma, cudaFuncAttributeMaxDynamicSharedMemorySize, 173568);

    prep_w4<<<dim3(16, 16, 4), 256>>>(Wq, Wk, Wv, Wo, WTh, WTl);
    prep_split<<<NSZ / 1024, 256>>>(x, Xh, Xl);

    // Q, K: single-pass fp16, fp16 output
    gemm_mma<1, 1><<<dim3(4, 64, 2), 256, 3 * 20480>>>(Xh, Xl, WTh, WTl,
                                                       bq, bk, bk, (void*)QKh, nullptr);
    // V: 3-term split, fp16 hi/lo output
    gemm_mma<3, 2><<<dim3(4, 64, 1), 256, 2 * 40960>>>(Xh, Xl, WTh + 2 * WSZ, WTl + 2 * WSZ,
                                                       bv, bv, bv, (void*)Vhp, Vlp);

    edge_mlp_mma<<<NEDGES / 512, 256>>>(ea, W1, b1, W2, b2, EBp);

    attn_mma<<<NGRAPHS * NHEADS, 256, 173568>>>(eidx);

    // O projection: 3-term split, fp32 output
    gemm_mma<3, 0><<<dim3(4, 64, 1), 256, 2 * 40960>>>(Oh, Ol, WTh + 3 * WSZ, WTl + 3 * WSZ,
                                                       bo, bo, bo, (void*)out, nullptr);
}

// round 16
// speedup vs baseline: 3.5900x; 1.1925x over previous
#include <cuda_runtime.h>
#include <cuda_bf16.h>
#include <cuda_fp16.h>
#include <cstdint>

#define D_MODEL 512
#define NHEADS  8
#define DK      64
#define NG      128
#define NGRAPHS 64
#define NNODES  8192
#define EPG     4096
#define NEDGES  262144
#define KPAD    40
#define W2PAD   520
#define NSZ     (NNODES * D_MODEL)
#define WSZ     (D_MODEL * D_MODEL)

// ---------------- scratch (static device allocations) ----------------------
__device__ float g_EB [NEDGES * NHEADS];

__device__ __half g_QKh[2 * NSZ];    // fp16 Q,K
__device__ __half g_Vh [NSZ];        // fp16 V
__device__ __half g_Xh [NSZ];        // fp16 x
__device__ __half g_Oh [NSZ];        // fp16 attention output
__device__ __half g_WThi[4 * WSZ];   // [n][k] transposed, hi
__device__ __half g_WTlo[4 * WSZ];   // lo

// ---------------- helpers ---------------------------------------------------
__device__ __forceinline__ uint32_t smem_u32(const void* p) {
    uint32_t a;
    asm("{ .reg .u64 t; cvta.to.shared.u64 t, %1; cvt.u32.u64 %0, t; }" : "=r"(a) : "l"(p));
    return a;
}
__device__ __forceinline__ void split_h(float v, __half& hi, __half& lo) {
    hi = __float2half_rn(v);
    lo = __float2half_rn(v - __half2float(hi));
}
__device__ __forceinline__ uint32_t pack_bf16x2(float lo_elem, float hi_elem) {
    uint32_t r;
    asm("cvt.rn.bf16x2.f32 %0, %1, %2;" : "=r"(r) : "f"(hi_elem), "f"(lo_elem));
    return r;
}
__device__ __forceinline__ void mma16816h(float* d, const uint32_t* a, uint32_t b0, uint32_t b1) {
    asm volatile(
        "mma.sync.aligned.m16n8k16.row.col.f32.f16.f16.f32 "
        "{%0,%1,%2,%3}, {%4,%5,%6,%7}, {%8,%9}, {%0,%1,%2,%3};"
        : "+f"(d[0]), "+f"(d[1]), "+f"(d[2]), "+f"(d[3])
        : "r"(a[0]), "r"(a[1]), "r"(a[2]), "r"(a[3]), "r"(b0), "r"(b1));
}
__device__ __forceinline__ void mma16816(float* d, const uint32_t* a, uint32_t b0, uint32_t b1) {
    asm volatile(
        "mma.sync.aligned.m16n8k16.row.col.f32.bf16.bf16.f32 "
        "{%0,%1,%2,%3}, {%4,%5,%6,%7}, {%8,%9}, {%0,%1,%2,%3};"
        : "+f"(d[0]), "+f"(d[1]), "+f"(d[2]), "+f"(d[3])
        : "r"(a[0]), "r"(a[1]), "r"(a[2]), "r"(a[3]), "r"(b0), "r"(b1));
}

#define CP16(dst, src) asm volatile("cp.async.cg.shared.global [%0], [%1], 16;" :: "r"(dst), "l"(src))
#define CPCOMMIT()     asm volatile("cp.async.commit_group;")
#define CPWAIT1()      asm volatile("cp.async.wait_group 1;")
#define CPWAIT0()      asm volatile("cp.async.wait_group 0;")
#define LDSM4(R0,R1,R2,R3,A) \
    asm volatile("ldmatrix.sync.aligned.m8n8.x4.shared.b16 {%0,%1,%2,%3}, [%4];" \
                 : "=r"(R0), "=r"(R1), "=r"(R2), "=r"(R3) : "r"(A))

// ---------------- prep: f32 -> f16 convert -----------------------------------
__global__ __launch_bounds__(256)
void prep_half(const float* __restrict__ X, __half* __restrict__ H) {
    int i = (blockIdx.x * 256 + threadIdx.x) * 4;
    float4 v = *(const float4*)(X + i);
    __half h[4] = {__float2half_rn(v.x), __float2half_rn(v.y),
                   __float2half_rn(v.z), __float2half_rn(v.w)};
    *(uint2*)(H + i) = *(uint2*)h;
}

// ---------------- prep: 4 weights transpose + split ---------------------------
__global__ __launch_bounds__(256)
void prep_w4(const float* __restrict__ W0, const float* __restrict__ W1p,
             const float* __restrict__ W2p, const float* __restrict__ W3,
             __half* __restrict__ Thi, __half* __restrict__ Tlo) {
    __shared__ float tile[32][33];
    const int z = blockIdx.z;
    const float* W = (z == 0) ? W0 : (z == 1) ? W1p : (z == 2) ? W2p : W3;
    __half* Th = Thi + (size_t)z * WSZ;
    __half* Tl = Tlo + (size_t)z * WSZ;
    const int k0 = blockIdx.y * 32, n0 = blockIdx.x * 32;
    const int tx = threadIdx.x & 31, ty = threadIdx.x >> 5;
    #pragma unroll
    for (int r = ty; r < 32; r += 8)
        tile[r][tx] = W[(size_t)(k0 + r) * D_MODEL + n0 + tx];
    __syncthreads();
    #pragma unroll
    for (int r = ty; r < 32; r += 8) {
        float v = tile[tx][r];
        __half h, l;
        split_h(v, h, l);
        size_t o = (size_t)(n0 + r) * D_MODEL + k0 + tx;
        Th[o] = h;
        Tl[o] = l;
    }
}

// ---------------- fp16 mma GEMM ------------------------------------------------
// NT=1: C = A @ Wh.  NT=2: C = A @ (Wh + Wl).  3-stage cp.async, 1 sync/iter.
// OUTM: 0 = f32 out, 1 = f16 out.  z selects weight slice / bias / C offset.
template <int NT, int OUTM>
__global__ __launch_bounds__(256, 2)
void gemm_mma(const __half* __restrict__ A,
              const __half* __restrict__ WTh, const __half* __restrict__ WTl,
              const float* __restrict__ bz0, const float* __restrict__ bz1,
              const float* __restrict__ bz2, void* __restrict__ Cb) {
    extern __shared__ char smc[];
    const uint32_t smb = smem_u32(smc);
    constexpr uint32_t STG = (NT == 2) ? 30720u : 20480u;

    const int z = blockIdx.z;
    const __half* Bhi = WTh + (size_t)z * WSZ;
    const __half* Blo = WTl + (size_t)z * WSZ;
    const float* bias = (z == 0) ? bz0 : (z == 1) ? bz1 : bz2;

    const int tid = threadIdx.x, lane = tid & 31, wid = tid >> 5;
    const int wm = (wid & 3) * 32, wn = (wid >> 2) * 64;
    const int bn = blockIdx.x * 128, bm = blockIdx.y * 128;
    const int grp = lane >> 2, th = lane & 3;

    const int lr  = tid >> 2;
    const int lcb = (tid & 3) * 16;

    const int l07 = lane & 7, q = lane >> 3;
    const uint32_t aOff = (uint32_t)(((wm + l07 + (q & 1) * 8) * KPAD + (q >> 1) * 8) * 2);
    const uint32_t bOff = (uint32_t)(((wn + l07 + (q >> 1) * 8) * KPAD + (q & 1) * 8) * 2);

    float acc[2][8][4];
    #pragma unroll
    for (int mi = 0; mi < 2; mi++)
        #pragma unroll
        for (int ni = 0; ni < 8; ni++)
            #pragma unroll
            for (int j = 0; j < 4; j++) acc[mi][ni][j] = 0.f;

    auto load_stage = [&](int s, int k0) {
        uint32_t sb = smb + (uint32_t)s * STG;
        #pragma unroll
        for (int p = 0; p < 2; p++) {
            int r = p * 64 + lr;
            uint32_t d = sb + (uint32_t)(r * 80 + lcb);
            CP16(d,         (const char*)(A   + (size_t)(bm + r) * D_MODEL + k0) + lcb);
            CP16(d + 10240, (const char*)(Bhi + (size_t)(bn + r) * D_MODEL + k0) + lcb);
            if (NT == 2)
                CP16(d + 20480, (const char*)(Blo + (size_t)(bn + r) * D_MODEL + k0) + lcb);
        }
    };

    auto do_compute = [&](uint32_t stb) {
        #pragma unroll
        for (int ks = 0; ks < 32; ks += 16) {
            uint32_t ah[2][4];
            uint32_t aAdr = stb + aOff + ks * 2;
            LDSM4(ah[0][0], ah[0][1], ah[0][2], ah[0][3], aAdr);
            LDSM4(ah[1][0], ah[1][1], ah[1][2], ah[1][3], aAdr + 1280);
            #pragma unroll
            for (int half = 0; half < 2; half++) {
                uint32_t bh[2][4], bu[2][4];
                #pragma unroll
                for (int p = 0; p < 2; p++) {
                    uint32_t bAdr = stb + 10240 + bOff + ks * 2 + (half * 2 + p) * 1280;
                    LDSM4(bh[p][0], bh[p][1], bh[p][2], bh[p][3], bAdr);
                    if (NT == 2) LDSM4(bu[p][0], bu[p][1], bu[p][2], bu[p][3], bAdr + 10240);
                }
                #pragma unroll
                for (int p = 0; p < 2; p++)
                    #pragma unroll
                    for (int mi = 0; mi < 2; mi++) {
                        const int ni = half * 4 + p * 2;
                        mma16816h(acc[mi][ni],     ah[mi], bh[p][0], bh[p][1]);
                        mma16816h(acc[mi][ni + 1], ah[mi], bh[p][2], bh[p][3]);
                    }
                if (NT == 2) {
                    #pragma unroll
                    for (int p = 0; p < 2; p++)
                        #pragma unroll
                        for (int mi = 0; mi < 2; mi++) {
                            const int ni = half * 4 + p * 2;
                            mma16816h(acc[mi][ni],     ah[mi], bu[p][0], bu[p][1]);
                            mma16816h(acc[mi][ni + 1], ah[mi], bu[p][2], bu[p][3]);
                        }
                }
            }
        }
    };

    load_stage(0, 0);  CPCOMMIT();
    load_stage(1, 32); CPCOMMIT();
    #pragma unroll 1
    for (int it = 0; it < 16; it++) {
        if (it < 14) CPWAIT1(); else CPWAIT0();
        __syncthreads();
        if (it + 2 < 16) { load_stage((it + 2) % 3, (it + 2) * 32); CPCOMMIT(); }
        do_compute(smb + (uint32_t)(it % 3) * STG);
    }

    #pragma unroll
    for (int mi = 0; mi < 2; mi++) {
        int row = bm + wm + mi * 16 + grp;
        #pragma unroll
        for (int ni = 0; ni < 8; ni++) {
            int col = bn + wn + ni * 8 + th * 2;
            float bx = bias[col], by = bias[col + 1];
            float v0 = acc[mi][ni][0] + bx, v1 = acc[mi][ni][1] + by;
            float v2 = acc[mi][ni][2] + bx, v3 = acc[mi][ni][3] + by;
            if constexpr (OUTM == 0) {
                float* C = (float*)Cb + (size_t)z * NSZ;
                *(float2*)&C[(size_t)row * D_MODEL + col]       = make_float2(v0, v1);
                *(float2*)&C[(size_t)(row + 8) * D_MODEL + col] = make_float2(v2, v3);
            } else {
                __half* C = (__half*)Cb + (size_t)z * NSZ;
                *(__half2*)&C[(size_t)row * D_MODEL + col]       = __floats2half2_rn(v0, v1);
                *(__half2*)&C[(size_t)(row + 8) * D_MODEL + col] = __floats2half2_rn(v2, v3);
            }
        }
    }
}

// ---------------- edge MLP on tensor cores: 64 edges/warp --------------------
__global__ __launch_bounds__(256)
void edge_mlp_mma(const float* __restrict__ ea,
                  const float* __restrict__ W1, const float* __restrict__ b1,
                  const float* __restrict__ W2, const float* __restrict__ b2,
                  float* __restrict__ eb) {
    __shared__ __nv_bfloat16 w1e[D_MODEL * 8];
    __shared__ __nv_bfloat16 w2t[8 * W2PAD];

    const int tid = threadIdx.x;
    for (int j = tid; j < D_MODEL; j += 256) {
        #pragma unroll
        for (int c = 0; c < 4; c++) w1e[j * 8 + c] = __float2bfloat16(W1[c * D_MODEL + j]);
        w1e[j * 8 + 4] = __float2bfloat16(b1[j]);
        w1e[j * 8 + 5] = __float2bfloat16(0.f);
        w1e[j * 8 + 6] = __float2bfloat16(0.f);
        w1e[j * 8 + 7] = __float2bfloat16(0.f);
        #pragma unroll
        for (int h = 0; h < 8; h++) w2t[h * W2PAD + j] = __float2bfloat16(W2[j * 8 + h]);
    }
    __syncthreads();

    const int lane = tid & 31, wid = tid >> 5;
    const int grp = lane >> 2, th = lane & 3;
    const int e0 = blockIdx.x * 512 + wid * 64;
    const uint32_t zero = 0;

    uint32_t ea0[4], ea1[4];
    if (th < 2) {
        #pragma unroll
        for (int t = 0; t < 4; t++) {
            float2 v0 = *(const float2*)(ea + (size_t)(e0 + t * 16 + grp) * 4 + th * 2);
            float2 v1 = *(const float2*)(ea + (size_t)(e0 + t * 16 + grp + 8) * 4 + th * 2);
            ea0[t] = pack_bf16x2(v0.x, v0.y);
            ea1[t] = pack_bf16x2(v1.x, v1.y);
        }
    } else if (th == 2) {
        uint32_t one = pack_bf16x2(1.f, 0.f);
        #pragma unroll
        for (int t = 0; t < 4; t++) { ea0[t] = one; ea1[t] = one; }
    } else {
        #pragma unroll
        for (int t = 0; t < 4; t++) { ea0[t] = 0u; ea1[t] = 0u; }
    }

    float acc[4][4];
    {
        float bz0 = b2[2 * th], bz1 = b2[2 * th + 1];
        #pragma unroll
        for (int t = 0; t < 4; t++) {
            acc[t][0] = bz0; acc[t][1] = bz1; acc[t][2] = bz0; acc[t][3] = bz1;
        }
    }

    #pragma unroll 2
    for (int jj = 0; jj < D_MODEL; jj += 16) {
        uint32_t ha[4][4];
        #pragma unroll
        for (int half = 0; half < 2; half++) {
            const int j0 = jj + half * 8;
            uint32_t w1f = *(const uint32_t*)&w1e[(j0 + grp) * 8 + th * 2];
            #pragma unroll
            for (int t = 0; t < 4; t++) {
                float c[4] = {0.f, 0.f, 0.f, 0.f};
                uint32_t av[4] = {ea0[t], ea1[t], zero, zero};
                mma16816(c, av, w1f, zero);
                ha[t][half * 2 + 0] = pack_bf16x2(fmaxf(c[0], 0.f), fmaxf(c[1], 0.f));
                ha[t][half * 2 + 1] = pack_bf16x2(fmaxf(c[2], 0.f), fmaxf(c[3], 0.f));
            }
        }
        uint32_t w2f0 = *(const uint32_t*)&w2t[grp * W2PAD + jj + th * 2];
        uint32_t w2f1 = *(const uint32_t*)&w2t[grp * W2PAD + jj + 8 + th * 2];
        #pragma unroll
        for (int t = 0; t < 4; t++) mma16816(acc[t], ha[t], w2f0, w2f1);
    }

    #pragma unroll
    for (int t = 0; t < 4; t++) {
        *(float2*)(eb + (size_t)(e0 + t * 16 + grp) * 8 + 2 * th) =
            make_float2(acc[t][0], acc[t][1]);
        *(float2*)(eb + (size_t)(e0 + t * 16 + grp + 8) * 8 + 2 * th) =
            make_float2(acc[t][2], acc[t][3]);
    }
}

// ---------------- tensorized block-diagonal attention ------------------------
// smem: S[128][130] f32 @0 (66560) | Q @66560 [128][72]h (18432) | K @84992 (18432)
// Ph @66560 [128][136]h (34816, aliases Q/K after use) | Pl @101376 (34816)
// Vh @136192 [64][136]h (17408) | invS @153600 (512). total 154112.
__global__ __launch_bounds__(256)
void attn_mma(const int* __restrict__ edge_index) {
    extern __shared__ char smc[];
    const uint32_t smb = smem_u32(smc);
    float*  S    = (float*)smc;
    __half* Qs   = (__half*)(smc + 66560);
    __half* Ks   = (__half*)(smc + 84992);
    __half* Phm  = (__half*)(smc + 66560);
    __half* Plm  = (__half*)(smc + 101376);
    __half* Vhs  = (__half*)(smc + 136192);
    float*  invS = (float*)(smc + 153600);

    const int g = blockIdx.x >> 3, h = blockIdx.x & 7;
    const int tid = threadIdx.x, lane = tid & 31, wid = tid >> 5;
    const int grp = lane >> 2, th = lane & 3;
    const int l07 = lane & 7, q = lane >> 3;

    const __half* Qg = g_QKh +       (size_t)(g * NG) * D_MODEL + h * DK;
    const __half* Kg = g_QKh + NSZ + (size_t)(g * NG) * D_MODEL + h * DK;
    const __half* Vg = g_Vh  +       (size_t)(g * NG) * D_MODEL + h * DK;
    #pragma unroll
    for (int idx = tid; idx < 1024; idx += 256) {
        int r = idx >> 3, c8 = (idx & 7) * 8;
        *(uint4*)&Qs[r * 72 + c8] = *(const uint4*)&Qg[(size_t)r * D_MODEL + c8];
        *(uint4*)&Ks[r * 72 + c8] = *(const uint4*)&Kg[(size_t)r * D_MODEL + c8];
        uint4 hv = *(const uint4*)&Vg[(size_t)r * D_MODEL + c8];
        const __half* hp = (const __half*)&hv;
        #pragma unroll
        for (int u = 0; u < 8; u++) Vhs[(c8 + u) * 136 + r] = hp[u];
    }
    __syncthreads();

    // ---- S = Q K^T * scale : warp tile 32x64
    {
        const int wm = (wid & 3) * 32, wn = (wid >> 2) * 64;
        uint32_t qOff = smb + 66560u + (uint32_t)(((wm + l07 + (q & 1) * 8) * 72 + (q >> 1) * 8) * 2);
        uint32_t kOff = smb + 84992u + (uint32_t)(((wn + l07 + (q >> 1) * 8) * 72 + (q & 1) * 8) * 2);

        float acc[2][8][4] = {};
        #pragma unroll
        for (int kk = 0; kk < 4; kk++) {
            uint32_t a0[4], a1[4];
            LDSM4(a0[0], a0[1], a0[2], a0[3], qOff + kk * 32);
            LDSM4(a1[0], a1[1], a1[2], a1[3], qOff + kk * 32 + 16 * 72 * 2);
            #pragma unroll
            for (int nip = 0; nip < 4; nip++) {
                uint32_t b0, b1, b2, b3;
                LDSM4(b0, b1, b2, b3, kOff + kk * 32 + nip * 16 * 72 * 2);
                mma16816h(acc[0][nip * 2],     a0, b0, b1);
                mma16816h(acc[0][nip * 2 + 1], a0, b2, b3);
                mma16816h(acc[1][nip * 2],     a1, b0, b1);
                mma16816h(acc[1][nip * 2 + 1], a1, b2, b3);
            }
        }
        #pragma unroll
        for (int mi = 0; mi < 2; mi++) {
            int r = wm + mi * 16 + grp;
            #pragma unroll
            for (int ni = 0; ni < 8; ni++) {
                int c = wn + ni * 8 + th * 2;
                *(float2*)&S[r * 130 + c] =
                    make_float2(acc[mi][ni][0] * 0.125f, acc[mi][ni][1] * 0.125f);
                *(float2*)&S[(r + 8) * 130 + c] =
                    make_float2(acc[mi][ni][2] * 0.125f, acc[mi][ni][3] * 0.125f);
            }
        }
    }
    __syncthreads();

    // ---- edge bias scatter
    const int* srcp = edge_index;
    const int* dstp = edge_index + NEDGES;
    for (int t = tid; t < EPG; t += 256) {
        int e = g * EPG + t;
        atomicAdd(&S[(srcp[e] & (NG - 1)) * 130 + (dstp[e] & (NG - 1))],
                  g_EB[(size_t)e * 8 + h]);
    }
    __syncthreads();

    // ---- softmax (2 threads/row) -> unnormalized P hi/lo (exact split), invS
    {
        const int i = tid >> 1, hf = tid & 1, jb = hf * 64;
        float m = -1e30f;
        for (int j = jb; j < jb + 64; j++) m = fmaxf(m, S[i * 130 + j]);
        m = fmaxf(m, __shfl_xor_sync(0xFFFFFFFFu, m, 1));
        float sum = 0.f;
        for (int j = jb; j < jb + 64; j += 2) {
            float p0 = __expf(S[i * 130 + j] - m);
            float p1 = __expf(S[i * 130 + j + 1] - m);
            sum += p0 + p1;
            __half h0, h1, l0, l1;
            split_h(p0, h0, l0);
            split_h(p1, h1, l1);
            __half hp[2] = {h0, h1}, lp[2] = {l0, l1};
            *(uint32_t*)&Phm[i * 136 + j] = *(uint32_t*)hp;
            *(uint32_t*)&Plm[i * 136 + j] = *(uint32_t*)lp;
        }
        sum += __shfl_xor_sync(0xFFFFFFFFu, sum, 1);
        if (hf == 0) invS[i] = 1.f / sum;
    }
    __syncthreads();

    // ---- out = (P V) * inv : warp tile 32x32, terms ph*V + pl*V
    {
        const int wm2 = (wid & 3) * 32, wn2 = (wid >> 2) * 32;
        uint32_t pOh = smb + 66560u  + (uint32_t)(((wm2 + l07 + (q & 1) * 8) * 136 + (q >> 1) * 8) * 2);
        uint32_t pOl = smb + 101376u + (uint32_t)(((wm2 + l07 + (q & 1) * 8) * 136 + (q >> 1) * 8) * 2);
        uint32_t vO  = smb + 136192u + (uint32_t)(((wn2 + l07 + (q >> 1) * 8) * 136 + (q & 1) * 8) * 2);

        float o[2][4][4] = {};
        #pragma unroll
        for (int kk = 0; kk < 8; kk++) {
            uint32_t ph[2][4], pl[2][4], vh[2][4];
            LDSM4(ph[0][0], ph[0][1], ph[0][2], ph[0][3], pOh + kk * 32);
            LDSM4(ph[1][0], ph[1][1], ph[1][2], ph[1][3], pOh + kk * 32 + 16 * 136 * 2);
            LDSM4(pl[0][0], pl[0][1], pl[0][2], pl[0][3], pOl + kk * 32);
            LDSM4(pl[1][0], pl[1][1], pl[1][2], pl[1][3], pOl + kk * 32 + 16 * 136 * 2);
            LDSM4(vh[0][0], vh[0][1], vh[0][2], vh[0][3], vO + kk * 32);
            LDSM4(vh[1][0], vh[1][1], vh[1][2], vh[1][3], vO + kk * 32 + 16 * 136 * 2);
            #pragma unroll
            for (int nip = 0; nip < 2; nip++)
                #pragma unroll
                for (int mi = 0; mi < 2; mi++) {
                    mma16816h(o[mi][nip * 2],     ph[mi], vh[nip][0], vh[nip][1]);
                    mma16816h(o[mi][nip * 2 + 1], ph[mi], vh[nip][2], vh[nip][3]);
                }
            #pragma unroll
            for (int nip = 0; nip < 2; nip++)
                #pragma unroll
                for (int mi = 0; mi < 2; mi++) {
                    mma16816h(o[mi][nip * 2],     pl[mi], vh[nip][0], vh[nip][1]);
                    mma16816h(o[mi][nip * 2 + 1], pl[mi], vh[nip][2], vh[nip][3]);
                }
        }

        #pragma unroll
        for (int mi = 0; mi < 2; mi++) {
            int r = wm2 + mi * 16 + grp;
            float iv0 = invS[r], iv1 = invS[r + 8];
            size_t b0 = (size_t)(g * NG + r) * D_MODEL + h * DK;
            size_t b1 = (size_t)(g * NG + r + 8) * D_MODEL + h * DK;
            #pragma unroll
            for (int ni = 0; ni < 4; ni++) {
                int c = wn2 + ni * 8 + th * 2;
                *(__half2*)&g_Oh[b0 + c] =
                    __floats2half2_rn(o[mi][ni][0] * iv0, o[mi][ni][1] * iv0);
                *(__half2*)&g_Oh[b1 + c] =
                    __floats2half2_rn(o[mi][ni][2] * iv1, o[mi][ni][3] * iv1);
            }
        }
    }
}

// ---------------- launcher ---------------------------------------------------
extern "C" void kernel_launch(void* const* d_in, const int* in_sizes, int n_in,
                              void* d_out, int out_size) {
    const float* x    = (const float*)d_in[0];
    const int*   eidx = (const int*)  d_in[1];
    const float* ea   = (const float*)d_in[2];
    const float* Wq = (const float*)d_in[5];
    const float* bq = (const float*)d_in[6];
    const float* Wk = (const float*)d_in[7];
    const float* bk = (const float*)d_in[8];
    const float* Wv = (const float*)d_in[9];
    const float* bv = (const float*)d_in[10];
    const float* Wo = (const float*)d_in[11];
    const float* bo = (const float*)d_in[12];
    const float* W1 = (const float*)d_in[13];
    const float* b1 = (const float*)d_in[14];
    const float* W2 = (const float*)d_in[15];
    const float* b2 = (const float*)d_in[16];
    float* out = (float*)d_out;

    float* EBp;
    __half *Xh, *Oh, *WTh, *WTl, *QKh, *Vhp;
    cudaGetSymbolAddress((void**)&EBp, g_EB);
    cudaGetSymbolAddress((void**)&Xh,  g_Xh);
    cudaGetSymbolAddress((void**)&Oh,  g_Oh);
    cudaGetSymbolAddress((void**)&WTh, g_WThi);
    cudaGetSymbolAddress((void**)&WTl, g_WTlo);
    cudaGetSymbolAddress((void**)&QKh, g_QKh);
    cudaGetSymbolAddress((void**)&Vhp, g_Vh);

    cudaFuncSetAttribute(gemm_mma<1, 1>, cudaFuncAttributeMaxDynamicSharedMemorySize, 3 * 20480);
    cudaFuncSetAttribute(gemm_mma<2, 1>, cudaFuncAttributeMaxDynamicSharedMemorySize, 3 * 30720);
    cudaFuncSetAttribute(gemm_mma<2, 0>, cudaFuncAttributeMaxDynamicSharedMemorySize, 3 * 30720);
    cudaFuncSetAttribute(attn_mma, cudaFuncAttributeMaxDynamicSharedMemorySize, 154112);

    prep_w4<<<dim3(16, 16, 4), 256>>>(Wq, Wk, Wv, Wo, WTh, WTl);
    prep_half<<<NSZ / 1024, 256>>>(x, Xh);

    // Q, K: single-term fp16 (softmax-damped), fp16 out
    gemm_mma<1, 1><<<dim3(4, 64, 2), 256, 3 * 20480>>>(Xh, WTh, WTl, bq, bk, bk, (void*)QKh);
    // V: 2-term (W hi/lo), fp16 out
    gemm_mma<2, 1><<<dim3(4, 64, 1), 256, 3 * 30720>>>(Xh, WTh + 2 * WSZ, WTl + 2 * WSZ,
                                                       bv, bv, bv, (void*)Vhp);

    edge_mlp_mma<<<NEDGES / 512, 256>>>(ea, W1, b1, W2, b2, EBp);

    attn_mma<<<NGRAPHS * NHEADS, 256, 154112>>>(eidx);

    // O projection: 2-term (W hi/lo), fp32 out
    gemm_mma<2, 0><<<dim3(4, 64, 1), 256, 3 * 30720>>>(Oh, WTh + 3 * WSZ, WTl + 3 * WSZ,
                                                       bo, bo, bo, (void*)out);
}